// round 6
// baseline (speedup 1.0000x reference)
#include <cuda_runtime.h>
#include <math.h>

// Problem constants
#define LSEQ 700
#define BATCH 32
#define DIN 41
#define HID 800
#define GATES 3200          // 4*HID
#define H2 1600             // 2*HID
#define NCOORD 2100         // 3*LSEQ

// ---------------- device scratch (allocation-free rule: __device__ globals) ---
__device__ float g_G0[2L * LSEQ * GATES * BATCH];   // [2][700][3200][32]
__device__ float g_G1[2L * LSEQ * GATES * BATCH];
__device__ float g_h0[LSEQ * H2 * BATCH];           // [700][1600][32]
__device__ float g_h1[LSEQ * H2 * BATCH];
__device__ float g_ang[LSEQ * BATCH * 3];
__device__ unsigned g_cnt[4];                       // barrier counters [layer*2+dir]
__device__ unsigned g_ack[4];

// ---------------- packed fp32x2 helpers --------------------------------------
__device__ __forceinline__ void ffma2(unsigned long long& d,
                                      unsigned long long a,
                                      unsigned long long b)
{
    asm("fma.rn.f32x2 %0, %1, %2, %3;" : "=l"(d) : "l"(a), "l"(b), "l"(d));
}
__device__ __forceinline__ unsigned long long add2(unsigned long long a,
                                                   unsigned long long b)
{
    unsigned long long r;
    asm("add.rn.f32x2 %0, %1, %2;" : "=l"(r) : "l"(a), "l"(b));
    return r;
}
__device__ __forceinline__ unsigned long long dupf(float x)
{
    unsigned long long r;
    asm("mov.b64 %0, {%1, %1};" : "=l"(r) : "f"(x));
    return r;
}
__device__ __forceinline__ float2 unpackf(unsigned long long u)
{
    float2 f;
    asm("mov.b64 {%0, %1}, %2;" : "=f"(f.x), "=f"(f.y) : "l"(u));
    return f;
}
__device__ __forceinline__ float sigf(float x) { return 1.f / (1.f + expf(-x)); }

// =============================================================================
// Tiled fp32 GEMM (f32x2 inner product) producing gate pre-activations
// G[dir][t][j][b].  (unchanged from passing R4/R5 kernel)
// =============================================================================
__global__ __launch_bounds__(256, 2)
void gemm_gates(const float* __restrict__ A, const float* __restrict__ B,
                const float* __restrict__ bias1, const float* __restrict__ bias2,
                float* __restrict__ Gout, int K, int ldb, int amode)
{
    __shared__ float As[16][128];
    __shared__ float Bs[16][128];
    int tid  = threadIdx.x;
    int row0 = blockIdx.y * 128;
    int col0 = blockIdx.x * 128;
    int tx = tid & 15, ty = tid >> 4;

    unsigned long long acc2[8][4];
#pragma unroll
    for (int m = 0; m < 8; m++)
#pragma unroll
        for (int n = 0; n < 4; n++) acc2[m][n] = 0ull;

    for (int kt = 0; kt < K; kt += 16) {
#pragma unroll
        for (int ii = 0; ii < 8; ii++) {
            int i = tid + 256 * ii;
            int kk = i >> 7, r = i & 127;
            int row = row0 + r;
            int k = kt + kk;
            float v = 0.f;
            if (k < K) {
                if (amode == 0) v = A[(row & 31) * (LSEQ * DIN) + (row >> 5) * DIN + k];
                else            v = A[(row >> 5) * (H2 * BATCH) + k * BATCH + (row & 31)];
            }
            As[kk][r] = v;
        }
#pragma unroll
        for (int ii = 0; ii < 8; ii++) {
            int i = tid + 256 * ii;
            int c = i >> 4, kk = i & 15;
            int k = kt + kk;
            Bs[kk][c] = (k < K) ? B[(col0 + c) * ldb + k] : 0.f;
        }
        __syncthreads();
#pragma unroll
        for (int kk = 0; kk < 16; kk++) {
            float a[8];
            *(float4*)&a[0] = *(const float4*)&As[kk][ty * 8];
            *(float4*)&a[4] = *(const float4*)&As[kk][ty * 8 + 4];
            ulonglong2 b01 = *(const ulonglong2*)&Bs[kk][tx * 8];
            ulonglong2 b23 = *(const ulonglong2*)&Bs[kk][tx * 8 + 4];
            unsigned long long bp[4] = { b01.x, b01.y, b23.x, b23.y };
#pragma unroll
            for (int m = 0; m < 8; m++) {
                unsigned long long am = dupf(a[m]);
#pragma unroll
                for (int n = 0; n < 4; n++) ffma2(acc2[m][n], am, bp[n]);
            }
        }
        __syncthreads();
    }

#pragma unroll
    for (int m = 0; m < 8; m++) {
        int row = row0 + ty * 8 + m;
        int t = row >> 5, b = row & 31;
#pragma unroll
        for (int n = 0; n < 4; n++) {
            float2 v = unpackf(acc2[m][n]);
            int c0 = col0 + tx * 8 + 2 * n;
#pragma unroll
            for (int q = 0; q < 2; q++) {
                int col = c0 + q;
                int dir = (col >= GATES) ? 1 : 0;
                int j = col - dir * GATES;
                float val = (q == 0 ? v.x : v.y) + bias1[col] + bias2[col];
                Gout[((dir * LSEQ + t) * GATES + j) * BATCH + b] = val;
            }
        }
    }
}

// =============================================================================
// Persistent bidirectional LSTM recurrence, smem-bandwidth-optimized.
// Grid 100 CTAs x 512 threads. CTA c: dir=c/50, units ubase..ubase+15.
// Per step: C[64 rows=(4g x 16u)][32 b] = W[64][800] x h[800][32].
// Thread (tile, kslab): tile=tid>>3 (8 rows x 4 batches), kslab=tid&7,
//   k = kk*8+kslab. Per k: 2xLDS.128 W (8 rows) + 1xLDS.128 h (4 b)
//   = 48B per 32 MAC (0.75 B/flop, was 1.5). K-slab partials reduced with
//   3 shfl-bfly rounds on packed f32x2, published via 8KB pb (overlaps hs).
// h staged in 160-k chunks (5/step), register-prefetched. Cell state in regs.
// =============================================================================
#define NCTA_DIR 50
#define HCH 160
#define NCHUNK (HID / HCH)                     // 5
#define SMEM_LSTM (64 * HID * 4 + HCH * 32 * 4)  // 204800 + 20480 = 225280

__global__ __launch_bounds__(512, 1)
void lstm_persist(const float* __restrict__ Whh, int layer)
{
    extern __shared__ char smem[];
    float* ws = (float*)smem;                      // [800][64]  (k-major rows)
    float* hs = (float*)(smem + 64 * HID * 4);     // [HCH][32]; pb overlaps
    float* pb = hs;                                // [64 rows][32 b]

    const float* G = layer ? g_G1 : g_G0;
    float* hout    = layer ? g_h1 : g_h0;

    int c   = blockIdx.x;
    int dir = c / NCTA_DIR;
    int ubase = (c % NCTA_DIR) * 16;
    int tid = threadIdx.x;

    // dot-phase mapping
    int tile  = tid >> 3;        // 0..63
    int kslab = tid & 7;         // 0..7
    int cg = tile >> 3;          // batch group: batches 4*cg..4*cg+3
    int rg = tile & 7;           // row group:   rows 8*rg..8*rg+7
    // cell-phase mapping
    int cu = tid >> 5;           // unit 0..15
    int cb = tid & 31;           // batch 0..31

    unsigned* cnt = &g_cnt[layer * 2 + dir];
    unsigned* ack = &g_ack[layer * 2 + dir];

    // ---- load Whh slice into smem (once): ws[k*64 + row], row = g*16+u ----
    const float* Wd = Whh + (long)dir * GATES * HID;
    for (int i = tid; i < 64 * HID; i += 512) {
        int row = i / HID;       // 0..63 (gmem-coalesced over k)
        int k   = i % HID;
        int gg = row >> 4, uu = row & 15;
        ws[k * 64 + row] = Wd[(long)(gg * HID + ubase + uu) * HID + k];
    }
    __syncthreads();

    float creg = 0.f;            // cell state for (cu, cb)

    for (int s = 0; s < LSEQ; s++) {
        int t = dir ? (LSEQ - 1 - s) : s;

        // G pre-activations (cell mapping), issued early
        long gb = ((long)(dir * LSEQ + t)) * GATES * BATCH;
        float gpre[4];
#pragma unroll
        for (int gg = 0; gg < 4; gg++)
            gpre[gg] = G[gb + (long)(gg * HID + ubase + cu) * BATCH + cb];

        float dsum[4] = {0.f, 0.f, 0.f, 0.f};     // recurrent contribution

        if (s > 0) {
            int tp = dir ? t + 1 : t - 1;
            const float* hp = hout + ((long)tp * H2 + dir * HID) * BATCH;
            const float2* hp2 = (const float2*)hp;

            unsigned long long acc[4][4];          // [unit-pair][batch]
#pragma unroll
            for (int up = 0; up < 4; up++)
#pragma unroll
                for (int bb = 0; bb < 4; bb++) acc[up][bb] = 0ull;

            // prefetch chunk 0 into registers
            float2 pr[5];
#pragma unroll
            for (int j = 0; j < 5; j++)
                pr[j] = __ldcg(hp2 + tid + 512 * j);

            for (int ch = 0; ch < NCHUNK; ch++) {
                __syncthreads();                   // hs free (prev chunk done)
#pragma unroll
                for (int j = 0; j < 5; j++)
                    ((float2*)hs)[tid + 512 * j] = pr[j];
                __syncthreads();                   // hs ready
                if (ch + 1 < NCHUNK) {
#pragma unroll
                    for (int j = 0; j < 5; j++)
                        pr[j] = __ldcg(hp2 + (ch + 1) * (HCH * 16) + tid + 512 * j);
                }
                int kbase = ch * HCH;
#pragma unroll
                for (int kk = 0; kk < HCH / 8; kk++) {
                    int koff = kk * 8 + kslab;
                    ulonglong2 wa = *(const ulonglong2*)(ws + (kbase + koff) * 64 + rg * 8);
                    ulonglong2 wb = *(const ulonglong2*)(ws + (kbase + koff) * 64 + rg * 8 + 4);
                    float4 hv = *(const float4*)(hs + koff * 32 + cg * 4);
                    unsigned long long h0 = dupf(hv.x);
                    unsigned long long h1 = dupf(hv.y);
                    unsigned long long h2 = dupf(hv.z);
                    unsigned long long h3 = dupf(hv.w);
                    ffma2(acc[0][0], wa.x, h0); ffma2(acc[0][1], wa.x, h1);
                    ffma2(acc[0][2], wa.x, h2); ffma2(acc[0][3], wa.x, h3);
                    ffma2(acc[1][0], wa.y, h0); ffma2(acc[1][1], wa.y, h1);
                    ffma2(acc[1][2], wa.y, h2); ffma2(acc[1][3], wa.y, h3);
                    ffma2(acc[2][0], wb.x, h0); ffma2(acc[2][1], wb.x, h1);
                    ffma2(acc[2][2], wb.x, h2); ffma2(acc[2][3], wb.x, h3);
                    ffma2(acc[3][0], wb.y, h0); ffma2(acc[3][1], wb.y, h1);
                    ffma2(acc[3][2], wb.y, h2); ffma2(acc[3][3], wb.y, h3);
                }
            }

            // ---- reduce over 8 k-slabs (3 bfly rounds, within warp) ----
#pragma unroll
            for (int o = 1; o < 8; o <<= 1) {
#pragma unroll
                for (int up = 0; up < 4; up++)
#pragma unroll
                    for (int bb = 0; bb < 4; bb++) {
                        unsigned long long other =
                            __shfl_xor_sync(0xffffffffu, acc[up][bb], o);
                        acc[up][bb] = add2(acc[up][bb], other);
                    }
            }

            // ---- publish: lane kslab writes row rg*8 + 2*(kslab>>1) + (kslab&1)
            __syncthreads();                       // last chunk compute done
            {
                int up  = kslab >> 1;
                int cmp = kslab & 1;
                float4 v;
                if (cmp == 0) {
                    v = make_float4(unpackf(acc[up][0]).x, unpackf(acc[up][1]).x,
                                    unpackf(acc[up][2]).x, unpackf(acc[up][3]).x);
                } else {
                    v = make_float4(unpackf(acc[up][0]).y, unpackf(acc[up][1]).y,
                                    unpackf(acc[up][2]).y, unpackf(acc[up][3]).y);
                }
                int row = rg * 8 + 2 * up + cmp;
                *(float4*)(pb + row * 32 + cg * 4) = v;
            }
            __syncthreads();                       // pb ready

            // ---- gather (cell mapping) ----
#pragma unroll
            for (int gg = 0; gg < 4; gg++)
                dsum[gg] = pb[(gg * 16 + cu) * 32 + cb];
        }

        // ---- LSTM cell ----
        float ai = gpre[0] + dsum[0];
        float af = gpre[1] + dsum[1];
        float ag = gpre[2] + dsum[2];
        float ao = gpre[3] + dsum[3];

        creg = sigf(af) * creg + sigf(ai) * tanhf(ag);
        float hv = sigf(ao) * tanhf(creg);
        __stcg(hout + ((long)t * H2 + dir * HID + ubase + cu) * BATCH + cb, hv);

        // ---- grid barrier over this direction's 50 CTAs ----
        __syncthreads();
        if (tid == 0) {
            asm volatile("red.release.gpu.global.add.u32 [%0], %1;"
                         :: "l"(cnt), "r"(1u) : "memory");
            unsigned target = (unsigned)(s + 1) * NCTA_DIR;
            unsigned v;
            do {
                asm volatile("ld.acquire.gpu.global.u32 %0, [%1];"
                             : "=r"(v) : "l"(cnt) : "memory");
            } while (v < target);
        }
        __syncthreads();
    }

    // ---- replay-safe counter reset via ack ----
    if (tid == 0) {
        asm volatile("red.release.gpu.global.add.u32 [%0], %1;"
                     :: "l"(ack), "r"(1u) : "memory");
        if ((c % NCTA_DIR) == 0) {
            unsigned v;
            do {
                asm volatile("ld.acquire.gpu.global.u32 %0, [%1];"
                             : "=r"(v) : "l"(ack) : "memory");
            } while (v < NCTA_DIR);
            *cnt = 0;
            *ack = 0;
            __threadfence();
        }
    }
}

// =============================================================================
// Fused head (k-chunk 160): linear -> softmax over BATCH dim -> angles.
// =============================================================================
#define HCHUNK 160
__global__ __launch_bounds__(640)
void head_kernel(const float* __restrict__ wlin, const float* __restrict__ blin,
                 const float* __restrict__ alphabet)
{
    int l = blockIdx.x;
    int tid = threadIdx.x;
    int j = tid >> 5, b = tid & 31;

    __shared__ float hs[HCHUNK * 32];
    __shared__ float ps[20][32];
    __shared__ float sa[60], ca[60];

    if (tid < 60) { float v = alphabet[tid]; sa[tid] = sinf(v); ca[tid] = cosf(v); }

    float acc = blin[j];
    const float* hb = g_h1 + (long)l * (H2 * BATCH);
    const float* w = wlin + j * H2;
    for (int k0 = 0; k0 < H2; k0 += HCHUNK) {
        __syncthreads();
#pragma unroll
        for (int i = 0; i < (HCHUNK * 32) / 640; i++)
            hs[tid + 640 * i] = hb[k0 * 32 + tid + 640 * i];
        __syncthreads();
#pragma unroll 8
        for (int k = 0; k < HCHUNK; k += 4) {
            float4 w4 = *(const float4*)(w + k0 + k);
            acc += w4.x * hs[(k + 0) * 32 + b];
            acc += w4.y * hs[(k + 1) * 32 + b];
            acc += w4.z * hs[(k + 2) * 32 + b];
            acc += w4.w * hs[(k + 3) * 32 + b];
        }
    }
    float m = acc;
#pragma unroll
    for (int o = 16; o; o >>= 1) m = fmaxf(m, __shfl_xor_sync(0xffffffffu, m, o));
    float e = expf(acc - m);
    float ssum = e;
#pragma unroll
    for (int o = 16; o; o >>= 1) ssum += __shfl_xor_sync(0xffffffffu, ssum, o);
    ps[j][b] = e / ssum;
    __syncthreads();

    if (tid < 96) {
        int b2 = tid / 3, i = tid - b2 * 3;
        float ssin = 0.f, scos = 0.f;
#pragma unroll
        for (int jj = 0; jj < 20; jj++) {
            float p = ps[jj][b2];
            ssin += p * sa[jj * 3 + i];
            scos += p * ca[jj * 3 + i];
        }
        g_ang[l * 96 + b2 * 3 + i] = atan2f(ssin, scos);
    }
}

// =============================================================================
// NeRF backbone extension (unchanged).
// =============================================================================
__global__ void nerf_kernel(float* __restrict__ out)
{
    int b = threadIdx.x;
    float ax = 0.f,   ay = 0.f,   az = 0.f;
    float bx = 100.f, by = 0.f,   bz = 0.f;
    float cx = 200.f, cy = 100.f, cz = 0.f;

    const float BL0 = 145.801f, BL1 = 152.326f, BL2 = 132.868f;
    const float TH0 = 2.124f,   TH1 = 1.941f,   TH2 = 2.028f;
    float d0a = -BL0 * cosf(TH0), d1a = BL0 * sinf(TH0);
    float d0b = -BL1 * cosf(TH1), d1b = BL1 * sinf(TH1);
    float d0c = -BL2 * cosf(TH2), d1c = BL2 * sinf(TH2);

    for (int s = 0; s < NCOORD; s++) {
        float phi = g_ang[s * 32 + b];
        int m = s - (s / 3) * 3;
        float d0 = (m == 0) ? d0a : (m == 1) ? d0b : d0c;
        float rs = (m == 0) ? d1a : (m == 1) ? d1b : d1c;

        float vx = cx - bx, vy = cy - by, vz = cz - bz;
        float inv = 1.f / (sqrtf(vx * vx + vy * vy + vz * vz) + 1e-12f);
        float bcx = vx * inv, bcy = vy * inv, bcz = vz * inv;

        float ux = bx - ax, uy = by - ay, uz = bz - az;
        float nx = uy * bcz - uz * bcy;
        float ny = uz * bcx - ux * bcz;
        float nz = ux * bcy - uy * bcx;
        float invn = 1.f / (sqrtf(nx * nx + ny * ny + nz * nz) + 1e-12f);
        nx *= invn; ny *= invn; nz *= invn;

        float mx = ny * bcz - nz * bcy;
        float my = nz * bcx - nx * bcz;
        float mz = nx * bcy - ny * bcx;

        float sp, cp;
        sincosf(phi, &sp, &cp);
        float d1 = rs * cp, d2 = rs * sp;

        float dx = cx + d0 * bcx + d1 * mx + d2 * nx;
        float dy = cy + d0 * bcy + d1 * my + d2 * ny;
        float dz = cz + d0 * bcz + d1 * mz + d2 * nz;

        out[s * 96 + b * 3 + 0] = dx;
        out[s * 96 + b * 3 + 1] = dy;
        out[s * 96 + b * 3 + 2] = dz;

        ax = bx; ay = by; az = bz;
        bx = cx; by = cy; bz = cz;
        cx = dx; cy = dy; cz = dz;
    }
}

// =============================================================================
extern "C" void kernel_launch(void* const* d_in, const int* in_sizes, int n_in,
                              void* d_out, int out_size)
{
    const float* x     = (const float*)d_in[0];
    const float* wih0  = (const float*)d_in[1];
    const float* whh0  = (const float*)d_in[2];
    const float* bih0  = (const float*)d_in[3];
    const float* bhh0  = (const float*)d_in[4];
    const float* wih1  = (const float*)d_in[5];
    const float* whh1  = (const float*)d_in[6];
    const float* bih1  = (const float*)d_in[7];
    const float* bhh1  = (const float*)d_in[8];
    const float* wlin  = (const float*)d_in[9];
    const float* blin  = (const float*)d_in[10];
    const float* alpha = (const float*)d_in[11];
    float* out = (float*)d_out;

    static int attr_done = 0;
    if (!attr_done) {
        cudaFuncSetAttribute(lstm_persist,
                             cudaFuncAttributeMaxDynamicSharedMemorySize, SMEM_LSTM);
        attr_done = 1;
    }

    dim3 gemm_grid(50, 175);   // N/128, M/128

    float* G0p; cudaGetSymbolAddress((void**)&G0p, g_G0);
    float* G1p; cudaGetSymbolAddress((void**)&G1p, g_G1);
    float* h0p; cudaGetSymbolAddress((void**)&h0p, g_h0);

    // Layer 0 input-side pre-activations: G0 = x @ Wih0^T + bih0 + bhh0
    gemm_gates<<<gemm_grid, 256>>>(x, wih0, bih0, bhh0, G0p, DIN, DIN, 0);

    // Layer 0 recurrence: single persistent launch (both directions)
    lstm_persist<<<100, 512, SMEM_LSTM>>>(whh0, 0);

    // Layer 1 input-side pre-activations: G1 = h0 @ Wih1^T + bih1 + bhh1
    gemm_gates<<<gemm_grid, 256>>>(h0p, wih1, bih1, bhh1, G1p, H2, H2, 1);

    // Layer 1 recurrence
    lstm_persist<<<100, 512, SMEM_LSTM>>>(whh1, 1);

    // Head: linear -> softmax(batch dim) -> angles
    head_kernel<<<LSEQ, 640>>>(wlin, blin, alpha);

    // NeRF extension -> output coords [2100][32][3]
    nerf_kernel<<<1, 32>>>(out);
}

// round 9
// speedup vs baseline: 3.4592x; 3.4592x over previous
#include <cuda_runtime.h>
#include <cuda_bf16.h>
#include <math.h>
#include <stdint.h>

// Problem constants
#define LSEQ 700
#define BATCH 32
#define DIN 41
#define HID 800
#define GATES 3200          // 4*HID
#define H2 1600             // 2*HID
#define NCOORD 2100         // 3*LSEQ

// ---------------- device scratch (allocation-free rule: __device__ globals) ---
__device__ float g_G0[2L * LSEQ * GATES * BATCH];   // [2][700][3200][32]
__device__ float g_G1[2L * LSEQ * GATES * BATCH];
__device__ float g_h0[LSEQ * H2 * BATCH];           // [700][1600][32]
__device__ float g_h1[LSEQ * H2 * BATCH];
__device__ float g_ang[LSEQ * BATCH * 3];
__device__ unsigned g_cnt[4];
__device__ unsigned g_ack[4];
// bf16-split operands for MMA GEMM (uint32 = 2 packed bf16, low = even k)
__device__ unsigned g_Ahi[22400 * 800];             // [row=t*32+b][k/2]
__device__ unsigned g_Alo[22400 * 800];
__device__ unsigned g_Bhi[6400 * 800];              // [col=dir*3200+j][k/2]
__device__ unsigned g_Blo[6400 * 800];

// ---------------- bf16 split helpers (explicit RNE bit ops) -------------------
__device__ __forceinline__ unsigned f2bf_rne(float x)
{
    unsigned u = __float_as_uint(x);
    unsigned r = (u + 0x7FFFu + ((u >> 16) & 1u)) >> 16;   // RNE to bf16
    return r & 0xFFFFu;
}
__device__ __forceinline__ float bf2f(unsigned b)
{
    return __uint_as_float(b << 16);
}
__device__ __forceinline__ void split2(float v0, float v1,
                                       unsigned& hi, unsigned& lo)
{
    unsigned h0 = f2bf_rne(v0), h1 = f2bf_rne(v1);
    unsigned l0 = f2bf_rne(v0 - bf2f(h0));
    unsigned l1 = f2bf_rne(v1 - bf2f(h1));
    hi = (h1 << 16) | h0;
    lo = (l1 << 16) | l0;
}

// ---------------- packed fp32x2 helpers --------------------------------------
__device__ __forceinline__ void ffma2(unsigned long long& d,
                                      unsigned long long a,
                                      unsigned long long b)
{
    asm("fma.rn.f32x2 %0, %1, %2, %3;" : "=l"(d) : "l"(a), "l"(b), "l"(d));
}
__device__ __forceinline__ unsigned long long dupf(float x)
{
    unsigned long long r;
    asm("mov.b64 %0, {%1, %1};" : "=l"(r) : "f"(x));
    return r;
}
__device__ __forceinline__ unsigned long long packf(float x, float y)
{
    unsigned long long r;
    asm("mov.b64 %0, {%1, %2};" : "=l"(r) : "f"(x), "f"(y));
    return r;
}
__device__ __forceinline__ float2 unpackf(unsigned long long u)
{
    float2 f;
    asm("mov.b64 {%0, %1}, %2;" : "=f"(f.x), "=f"(f.y) : "l"(u));
    return f;
}
__device__ __forceinline__ float sigf(float x) { return 1.f / (1.f + expf(-x)); }

// ---------------- warp MMA (baseline PTX, compiles at compute_103) ------------
__device__ __forceinline__ void mma16816(float* d, const unsigned* a,
                                         const unsigned* b)
{
    asm volatile(
        "mma.sync.aligned.m16n8k16.row.col.f32.bf16.bf16.f32 "
        "{%0,%1,%2,%3}, {%4,%5,%6,%7}, {%8,%9}, {%0,%1,%2,%3};"
        : "+f"(d[0]), "+f"(d[1]), "+f"(d[2]), "+f"(d[3])
        : "r"(a[0]), "r"(a[1]), "r"(a[2]), "r"(a[3]), "r"(b[0]), "r"(b[1]));
}

// =============================================================================
// Tiled fp32 GEMM (f32x2) — used ONLY for layer 0 (K=41).
// =============================================================================
__global__ __launch_bounds__(256, 2)
void gemm_gates(const float* __restrict__ A, const float* __restrict__ B,
                const float* __restrict__ bias1, const float* __restrict__ bias2,
                float* __restrict__ Gout, int K, int ldb, int amode)
{
    __shared__ float As[16][128];
    __shared__ float Bs[16][128];
    int tid  = threadIdx.x;
    int row0 = blockIdx.y * 128;
    int col0 = blockIdx.x * 128;
    int tx = tid & 15, ty = tid >> 4;

    unsigned long long acc2[8][4];
#pragma unroll
    for (int m = 0; m < 8; m++)
#pragma unroll
        for (int n = 0; n < 4; n++) acc2[m][n] = 0ull;

    for (int kt = 0; kt < K; kt += 16) {
#pragma unroll
        for (int ii = 0; ii < 8; ii++) {
            int i = tid + 256 * ii;
            int kk = i >> 7, r = i & 127;
            int row = row0 + r;
            int k = kt + kk;
            float v = 0.f;
            if (k < K) {
                if (amode == 0) v = A[(row & 31) * (LSEQ * DIN) + (row >> 5) * DIN + k];
                else            v = A[(row >> 5) * (H2 * BATCH) + k * BATCH + (row & 31)];
            }
            As[kk][r] = v;
        }
#pragma unroll
        for (int ii = 0; ii < 8; ii++) {
            int i = tid + 256 * ii;
            int c = i >> 4, kk = i & 15;
            int k = kt + kk;
            Bs[kk][c] = (k < K) ? B[(col0 + c) * ldb + k] : 0.f;
        }
        __syncthreads();
#pragma unroll
        for (int kk = 0; kk < 16; kk++) {
            float a[8];
            *(float4*)&a[0] = *(const float4*)&As[kk][ty * 8];
            *(float4*)&a[4] = *(const float4*)&As[kk][ty * 8 + 4];
            ulonglong2 b01 = *(const ulonglong2*)&Bs[kk][tx * 8];
            ulonglong2 b23 = *(const ulonglong2*)&Bs[kk][tx * 8 + 4];
            unsigned long long bp[4] = { b01.x, b01.y, b23.x, b23.y };
#pragma unroll
            for (int m = 0; m < 8; m++) {
                unsigned long long am = dupf(a[m]);
#pragma unroll
                for (int n = 0; n < 4; n++) ffma2(acc2[m][n], am, bp[n]);
            }
        }
        __syncthreads();
    }

#pragma unroll
    for (int m = 0; m < 8; m++) {
        int row = row0 + ty * 8 + m;
        int t = row >> 5, b = row & 31;
#pragma unroll
        for (int n = 0; n < 4; n++) {
            float2 v = unpackf(acc2[m][n]);
            int c0 = col0 + tx * 8 + 2 * n;
#pragma unroll
            for (int q = 0; q < 2; q++) {
                int col = c0 + q;
                int dir = (col >= GATES) ? 1 : 0;
                int j = col - dir * GATES;
                float val = (q == 0 ? v.x : v.y) + bias1[col] + bias2[col];
                Gout[((dir * LSEQ + t) * GATES + j) * BATCH + b] = val;
            }
        }
    }
}

// =============================================================================
// conv_w: Wih1 [6400][1600] f32 -> Bhi/Blo packed bf16 pairs [6400][800].
// =============================================================================
__global__ __launch_bounds__(256)
void conv_w(const float* __restrict__ W)
{
    long i = (long)blockIdx.x * 256 + threadIdx.x;
    if (i >= 6400L * 800) return;
    float2 v = *(const float2*)(W + 2 * i);
    unsigned hi, lo;
    split2(v.x, v.y, hi, lo);
    g_Bhi[i] = hi;
    g_Blo[i] = lo;
}

// =============================================================================
// conv_h: h0 [t][k][b] f32 -> Ahi/Alo [row=t*32+b][k/2] packed bf16 pairs.
// =============================================================================
__global__ __launch_bounds__(256)
void conv_h(void)
{
    __shared__ float hsm[320 * 32];
    int t = blockIdx.x;
    int tid = threadIdx.x;
    const float* src = g_h0 + (long)t * (H2 * BATCH);
    for (int slab = 0; slab < 5; slab++) {
        __syncthreads();
#pragma unroll
        for (int i = 0; i < 40; i++)
            hsm[tid + 256 * i] = src[slab * (320 * 32) + tid + 256 * i];
        __syncthreads();
        for (int i = tid; i < 32 * 160; i += 256) {
            int b = i / 160, kp = i - b * 160;
            float v0 = hsm[(2 * kp) * 32 + b];
            float v1 = hsm[(2 * kp + 1) * 32 + b];
            unsigned hi, lo;
            split2(v0, v1, hi, lo);
            long o = (long)(t * 32 + b) * 800 + slab * 160 + kp;
            g_Ahi[o] = hi;
            g_Alo[o] = lo;
        }
    }
}

// =============================================================================
// gemm1_mma: G1 = h0 @ Wih1^T + biases via bf16-split warp MMA (m16n8k16).
// Grid (50 col-tiles x 175 row-tiles), 256 threads = 8 warps.
// CTA tile 128 rows x 128 cols; warp tile 32 x 64 (2 x 8 m16n8 tiles).
// K = 1600 in 25 chunks of 64 (32 packed b32). Smem stride 36 words:
//   staging banks (4r + kq) distinct; frag-load banks (4g + tig) distinct.
// 3 split passes per k16: Ahi*Bhi + Ahi*Blo + Alo*Bhi; fp32 accumulators.
// =============================================================================
#define MM_STRIDE 36
#define MM_ASZ (128 * MM_STRIDE)                    // words per operand buffer
#define MM_SMEM (4 * MM_ASZ * 4)                    // 73728 bytes

__global__ __launch_bounds__(256, 2)
void gemm1_mma(const float* __restrict__ bias1, const float* __restrict__ bias2,
               float* __restrict__ Gout)
{
    extern __shared__ unsigned sm[];
    unsigned* Ah = sm;
    unsigned* Al = Ah + MM_ASZ;
    unsigned* Bh = Al + MM_ASZ;
    unsigned* Bl = Bh + MM_ASZ;

    int tid = threadIdx.x;
    int wid = tid >> 5, lane = tid & 31;
    int g = lane >> 2, tig = lane & 3;
    int col0 = blockIdx.x * 128;
    int row0 = blockIdx.y * 128;
    int m0 = (wid & 3) * 32;           // warp row offset within CTA tile
    int n0 = (wid >> 2) * 64;          // warp col offset

    float acc[2][8][4];
#pragma unroll
    for (int mt = 0; mt < 2; mt++)
#pragma unroll
        for (int nt = 0; nt < 8; nt++)
#pragma unroll
            for (int q = 0; q < 4; q++) acc[mt][nt][q] = 0.f;

    int sr = tid >> 4, skq = tid & 15;               // staging coords

    for (int ch = 0; ch < 25; ch++) {
        __syncthreads();
        // ---- stage chunk: A rows row0..row0+127, B rows col0..col0+127 ----
#pragma unroll
        for (int it = 0; it < 8; it++) {
            int rr = sr + it * 16;
            long ao = (long)(row0 + rr) * 800 + ch * 32 + 2 * skq;
            long bo = (long)(col0 + rr) * 800 + ch * 32 + 2 * skq;
            *(uint2*)(Ah + rr * MM_STRIDE + 2 * skq) = *(const uint2*)(g_Ahi + ao);
            *(uint2*)(Al + rr * MM_STRIDE + 2 * skq) = *(const uint2*)(g_Alo + ao);
            *(uint2*)(Bh + rr * MM_STRIDE + 2 * skq) = *(const uint2*)(g_Bhi + bo);
            *(uint2*)(Bl + rr * MM_STRIDE + 2 * skq) = *(const uint2*)(g_Blo + bo);
        }
        __syncthreads();

#pragma unroll
        for (int kk = 0; kk < 4; kk++) {
            int kpb = kk * 8;
            // B fragments for all 8 n-tiles (hi + lo)
            unsigned bh[8][2], bl[8][2];
#pragma unroll
            for (int nt = 0; nt < 8; nt++) {
                int br = (n0 + nt * 8 + g) * MM_STRIDE + kpb + tig;
                bh[nt][0] = Bh[br];     bh[nt][1] = Bh[br + 4];
                bl[nt][0] = Bl[br];     bl[nt][1] = Bl[br + 4];
            }
#pragma unroll
            for (int mt = 0; mt < 2; mt++) {
                int ar0 = (m0 + mt * 16 + g) * MM_STRIDE + kpb + tig;
                int ar1 = ar0 + 8 * MM_STRIDE;
                unsigned ah[4] = { Ah[ar0], Ah[ar1], Ah[ar0 + 4], Ah[ar1 + 4] };
                unsigned al[4] = { Al[ar0], Al[ar1], Al[ar0 + 4], Al[ar1 + 4] };
#pragma unroll
                for (int nt = 0; nt < 8; nt++) {
                    mma16816(acc[mt][nt], ah, bh[nt]);
                    mma16816(acc[mt][nt], ah, bl[nt]);
                    mma16816(acc[mt][nt], al, bh[nt]);
                }
            }
        }
    }

    // ---- epilogue: biases + scatter to G layout ----
#pragma unroll
    for (int mt = 0; mt < 2; mt++) {
        int r0 = row0 + m0 + mt * 16 + g;
        int r1 = r0 + 8;
        int t0 = r0 >> 5, b0 = r0 & 31;
        int t1 = r1 >> 5, b1 = r1 & 31;
#pragma unroll
        for (int nt = 0; nt < 8; nt++) {
            int c0 = col0 + n0 + nt * 8 + 2 * tig;
#pragma unroll
            for (int q = 0; q < 2; q++) {
                int col = c0 + q;
                int dir = (col >= GATES) ? 1 : 0;
                int j = col - dir * GATES;
                float bb = bias1[col] + bias2[col];
                long base = ((long)(dir * LSEQ) * GATES) * BATCH * 0 +
                            ((long)(dir * LSEQ + t0) * GATES + j) * BATCH + b0;
                Gout[base] = acc[mt][nt][q] + bb;
                Gout[((long)(dir * LSEQ + t1) * GATES + j) * BATCH + b1] =
                    acc[mt][nt][2 + q] + bb;
            }
        }
    }
}

// =============================================================================
// Persistent bidirectional LSTM recurrence — R5 version verbatim (proven).
// =============================================================================
#define RBK 80
#define NCTA_DIR 50
#define SMEM_LSTM (8 * 4 * HID * 8 + RBK * 32 * 4)

__global__ __launch_bounds__(256, 1)
void lstm_persist(const float* __restrict__ Whh, int layer)
{
    extern __shared__ char smemc[];
    float2* ws = (float2*)smemc;
    float*  hs = (float*)(smemc + 8 * 4 * HID * 8);

    const float* G = layer ? g_G1 : g_G0;
    float* hout    = layer ? g_h1 : g_h0;

    int c   = blockIdx.x;
    int dir = c / NCTA_DIR;
    int ubase = (c % NCTA_DIR) * 16;
    int tid = threadIdx.x;
    int b = tid & 31, ul = tid >> 5;
    int u0 = ubase + 2 * ul;

    unsigned* cnt = &g_cnt[layer * 2 + dir];
    unsigned* ack = &g_ack[layer * 2 + dir];

    const float* Wd = Whh + (long)dir * GATES * HID;
    for (int i = tid; i < 8 * 4 * HID; i += 256) {
        int k = i % HID;
        int pg = i / HID;
        int p = pg >> 2, g = pg & 3;
        int urow0 = g * HID + ubase + 2 * p;
        ws[i] = make_float2(Wd[(long)urow0 * HID + k], Wd[(long)(urow0 + 1) * HID + k]);
    }
    __syncthreads();

    float c0r = 0.f, c1r = 0.f;

    for (int s = 0; s < LSEQ; s++) {
        int t = dir ? (LSEQ - 1 - s) : s;

        long gb = ((long)(dir * LSEQ + t)) * GATES * BATCH;
        unsigned long long acc[4];
#pragma unroll
        for (int g = 0; g < 4; g++) {
            float v0 = G[gb + (long)(g * HID + u0) * BATCH + b];
            float v1 = G[gb + (long)(g * HID + u0 + 1) * BATCH + b];
            acc[g] = packf(v0, v1);
        }

        if (s > 0) {
            int tp = dir ? t + 1 : t - 1;
            const float* hp = hout + ((long)tp * H2 + dir * HID) * BATCH;
            for (int k0 = 0; k0 < HID; k0 += RBK) {
                __syncthreads();
#pragma unroll
                for (int i = 0; i < (RBK * 32) / 256; i++)
                    hs[tid + 256 * i] = __ldcg(hp + k0 * 32 + tid + 256 * i);
                __syncthreads();
#pragma unroll 4
                for (int k = 0; k < RBK; k += 2) {
                    unsigned long long h0d = dupf(hs[k * 32 + b]);
                    unsigned long long h1d = dupf(hs[k * 32 + 32 + b]);
#pragma unroll
                    for (int g = 0; g < 4; g++) {
                        ulonglong2 w2 = *(const ulonglong2*)(ws + (ul * 4 + g) * HID + k0 + k);
                        ffma2(acc[g], w2.x, h0d);
                        ffma2(acc[g], w2.y, h1d);
                    }
                }
            }
        }

        float2 ai = unpackf(acc[0]);
        float2 af = unpackf(acc[1]);
        float2 ag = unpackf(acc[2]);
        float2 ao = unpackf(acc[3]);

        c0r = sigf(af.x) * c0r + sigf(ai.x) * tanhf(ag.x);
        c1r = sigf(af.y) * c1r + sigf(ai.y) * tanhf(ag.y);
        float h0v = sigf(ao.x) * tanhf(c0r);
        float h1v = sigf(ao.y) * tanhf(c1r);

        long hix = ((long)t * H2 + dir * HID + u0) * BATCH + b;
        __stcg(hout + hix, h0v);
        __stcg(hout + hix + BATCH, h1v);

        __syncthreads();
        if (tid == 0) {
            asm volatile("red.release.gpu.global.add.u32 [%0], %1;"
                         :: "l"(cnt), "r"(1u) : "memory");
            unsigned target = (unsigned)(s + 1) * NCTA_DIR;
            unsigned v;
            do {
                asm volatile("ld.acquire.gpu.global.u32 %0, [%1];"
                             : "=r"(v) : "l"(cnt) : "memory");
            } while (v < target);
        }
        __syncthreads();
    }

    if (tid == 0) {
        asm volatile("red.release.gpu.global.add.u32 [%0], %1;"
                     :: "l"(ack), "r"(1u) : "memory");
        if ((c % NCTA_DIR) == 0) {
            unsigned v;
            do {
                asm volatile("ld.acquire.gpu.global.u32 %0, [%1];"
                             : "=r"(v) : "l"(ack) : "memory");
            } while (v < NCTA_DIR);
            *cnt = 0;
            *ack = 0;
            __threadfence();
        }
    }
}

// =============================================================================
// Fused head (k-chunk 160): linear -> softmax over BATCH dim -> angles.
// =============================================================================
#define HCHUNK 160
__global__ __launch_bounds__(640)
void head_kernel(const float* __restrict__ wlin, const float* __restrict__ blin,
                 const float* __restrict__ alphabet)
{
    int l = blockIdx.x;
    int tid = threadIdx.x;
    int j = tid >> 5, b = tid & 31;

    __shared__ float hs[HCHUNK * 32];
    __shared__ float ps[20][32];
    __shared__ float sa[60], ca[60];

    if (tid < 60) { float v = alphabet[tid]; sa[tid] = sinf(v); ca[tid] = cosf(v); }

    float acc = blin[j];
    const float* hb = g_h1 + (long)l * (H2 * BATCH);
    const float* w = wlin + j * H2;
    for (int k0 = 0; k0 < H2; k0 += HCHUNK) {
        __syncthreads();
#pragma unroll
        for (int i = 0; i < (HCHUNK * 32) / 640; i++)
            hs[tid + 640 * i] = hb[k0 * 32 + tid + 640 * i];
        __syncthreads();
#pragma unroll 8
        for (int k = 0; k < HCHUNK; k += 4) {
            float4 w4 = *(const float4*)(w + k0 + k);
            acc += w4.x * hs[(k + 0) * 32 + b];
            acc += w4.y * hs[(k + 1) * 32 + b];
            acc += w4.z * hs[(k + 2) * 32 + b];
            acc += w4.w * hs[(k + 3) * 32 + b];
        }
    }
    float m = acc;
#pragma unroll
    for (int o = 16; o; o >>= 1) m = fmaxf(m, __shfl_xor_sync(0xffffffffu, m, o));
    float e = expf(acc - m);
    float ssum = e;
#pragma unroll
    for (int o = 16; o; o >>= 1) ssum += __shfl_xor_sync(0xffffffffu, ssum, o);
    ps[j][b] = e / ssum;
    __syncthreads();

    if (tid < 96) {
        int b2 = tid / 3, i = tid - b2 * 3;
        float ssin = 0.f, scos = 0.f;
#pragma unroll
        for (int jj = 0; jj < 20; jj++) {
            float p = ps[jj][b2];
            ssin += p * sa[jj * 3 + i];
            scos += p * ca[jj * 3 + i];
        }
        g_ang[l * 96 + b2 * 3 + i] = atan2f(ssin, scos);
    }
}

// =============================================================================
// NeRF backbone extension (unchanged).
// =============================================================================
__global__ void nerf_kernel(float* __restrict__ out)
{
    int b = threadIdx.x;
    float ax = 0.f,   ay = 0.f,   az = 0.f;
    float bx = 100.f, by = 0.f,   bz = 0.f;
    float cx = 200.f, cy = 100.f, cz = 0.f;

    const float BL0 = 145.801f, BL1 = 152.326f, BL2 = 132.868f;
    const float TH0 = 2.124f,   TH1 = 1.941f,   TH2 = 2.028f;
    float d0a = -BL0 * cosf(TH0), d1a = BL0 * sinf(TH0);
    float d0b = -BL1 * cosf(TH1), d1b = BL1 * sinf(TH1);
    float d0c = -BL2 * cosf(TH2), d1c = BL2 * sinf(TH2);

    for (int s = 0; s < NCOORD; s++) {
        float phi = g_ang[s * 32 + b];
        int m = s - (s / 3) * 3;
        float d0 = (m == 0) ? d0a : (m == 1) ? d0b : d0c;
        float rs = (m == 0) ? d1a : (m == 1) ? d1b : d1c;

        float vx = cx - bx, vy = cy - by, vz = cz - bz;
        float inv = 1.f / (sqrtf(vx * vx + vy * vy + vz * vz) + 1e-12f);
        float bcx = vx * inv, bcy = vy * inv, bcz = vz * inv;

        float ux = bx - ax, uy = by - ay, uz = bz - az;
        float nx = uy * bcz - uz * bcy;
        float ny = uz * bcx - ux * bcz;
        float nz = ux * bcy - uy * bcx;
        float invn = 1.f / (sqrtf(nx * nx + ny * ny + nz * nz) + 1e-12f);
        nx *= invn; ny *= invn; nz *= invn;

        float mx = ny * bcz - nz * bcy;
        float my = nz * bcx - nx * bcz;
        float mz = nx * bcy - ny * bcx;

        float sp, cp;
        sincosf(phi, &sp, &cp);
        float d1 = rs * cp, d2 = rs * sp;

        float dx = cx + d0 * bcx + d1 * mx + d2 * nx;
        float dy = cy + d0 * bcy + d1 * my + d2 * ny;
        float dz = cz + d0 * bcz + d1 * mz + d2 * nz;

        out[s * 96 + b * 3 + 0] = dx;
        out[s * 96 + b * 3 + 1] = dy;
        out[s * 96 + b * 3 + 2] = dz;

        ax = bx; ay = by; az = bz;
        bx = cx; by = cy; bz = cz;
        cx = dx; cy = dy; cz = dz;
    }
}

// =============================================================================
extern "C" void kernel_launch(void* const* d_in, const int* in_sizes, int n_in,
                              void* d_out, int out_size)
{
    const float* x     = (const float*)d_in[0];
    const float* wih0  = (const float*)d_in[1];
    const float* whh0  = (const float*)d_in[2];
    const float* bih0  = (const float*)d_in[3];
    const float* bhh0  = (const float*)d_in[4];
    const float* wih1  = (const float*)d_in[5];
    const float* whh1  = (const float*)d_in[6];
    const float* bih1  = (const float*)d_in[7];
    const float* bhh1  = (const float*)d_in[8];
    const float* wlin  = (const float*)d_in[9];
    const float* blin  = (const float*)d_in[10];
    const float* alpha = (const float*)d_in[11];
    float* out = (float*)d_out;

    static int attr_done = 0;
    if (!attr_done) {
        cudaFuncSetAttribute(lstm_persist,
                             cudaFuncAttributeMaxDynamicSharedMemorySize, SMEM_LSTM);
        cudaFuncSetAttribute(gemm1_mma,
                             cudaFuncAttributeMaxDynamicSharedMemorySize, MM_SMEM);
        attr_done = 1;
    }

    float* G0p; cudaGetSymbolAddress((void**)&G0p, g_G0);
    float* G1p; cudaGetSymbolAddress((void**)&G1p, g_G1);

    // Layer 0 input-side pre-activations: G0 = x @ Wih0^T + biases (fp32, K=41)
    gemm_gates<<<dim3(50, 175), 256>>>(x, wih0, bih0, bhh0, G0p, DIN, DIN, 0);

    // Weight conversion for layer-1 GEMM (independent of lstm0)
    conv_w<<<20000, 256>>>(wih1);

    // Layer 0 recurrence
    lstm_persist<<<100, 256, SMEM_LSTM>>>(whh0, 0);

    // h0 -> bf16 hi/lo row-major
    conv_h<<<LSEQ, 256>>>();

    // Layer 1 input-side pre-activations via bf16-split warp MMA
    gemm1_mma<<<dim3(50, 175), 256, MM_SMEM>>>(bih1, bhh1, G1p);

    // Layer 1 recurrence
    lstm_persist<<<100, 256, SMEM_LSTM>>>(whh1, 1);

    // Head: linear -> softmax(batch dim) -> angles
    head_kernel<<<LSEQ, 640>>>(wlin, blin, alpha);

    // NeRF extension -> output coords [2100][32][3]
    nerf_kernel<<<1, 32>>>(out);
}

// round 11
// speedup vs baseline: 5.6569x; 1.6353x over previous
#include <cuda_runtime.h>
#include <cuda_bf16.h>
#include <math.h>
#include <stdint.h>

// Problem constants
#define LSEQ 700
#define BATCH 32
#define DIN 41
#define HID 800
#define GATES 3200          // 4*HID
#define H2 1600             // 2*HID
#define NCOORD 2100         // 3*LSEQ

// ---------------- device scratch (allocation-free rule: __device__ globals) ---
__device__ float g_G0[2L * LSEQ * GATES * BATCH];   // [2][700][3200][32]
__device__ float g_G1[2L * LSEQ * GATES * BATCH];
__device__ float g_h0[LSEQ * H2 * BATCH];           // [700][1600][32]
__device__ float g_h1[LSEQ * H2 * BATCH];
__device__ float g_ang[LSEQ * BATCH * 3];
__device__ unsigned g_cnt[4];
__device__ unsigned g_ack[4];
// bf16-split operands for layer-1 input GEMM
__device__ unsigned g_Ahi[22400 * 800];             // [row=t*32+b][k/2]
__device__ unsigned g_Alo[22400 * 800];
__device__ unsigned g_Bhi[6400 * 800];              // [col=dir*3200+j][k/2]
__device__ unsigned g_Blo[6400 * 800];
// bf16-split h state for recurrence MMA: [dir][batch][k/2]
__device__ unsigned g_hbf_hi[2 * 32 * 400];
__device__ unsigned g_hbf_lo[2 * 32 * 400];

// ---------------- bf16 split helpers (explicit RNE bit ops) -------------------
__device__ __forceinline__ unsigned f2bf_rne(float x)
{
    unsigned u = __float_as_uint(x);
    unsigned r = (u + 0x7FFFu + ((u >> 16) & 1u)) >> 16;   // RNE to bf16
    return r & 0xFFFFu;
}
__device__ __forceinline__ float bf2f(unsigned b)
{
    return __uint_as_float(b << 16);
}
__device__ __forceinline__ void split2(float v0, float v1,
                                       unsigned& hi, unsigned& lo)
{
    unsigned h0 = f2bf_rne(v0), h1 = f2bf_rne(v1);
    unsigned l0 = f2bf_rne(v0 - bf2f(h0));
    unsigned l1 = f2bf_rne(v1 - bf2f(h1));
    hi = (h1 << 16) | h0;
    lo = (l1 << 16) | l0;
}

// ---------------- packed fp32x2 helpers --------------------------------------
__device__ __forceinline__ void ffma2(unsigned long long& d,
                                      unsigned long long a,
                                      unsigned long long b)
{
    asm("fma.rn.f32x2 %0, %1, %2, %3;" : "=l"(d) : "l"(a), "l"(b), "l"(d));
}
__device__ __forceinline__ unsigned long long dupf(float x)
{
    unsigned long long r;
    asm("mov.b64 %0, {%1, %1};" : "=l"(r) : "f"(x));
    return r;
}
__device__ __forceinline__ float2 unpackf(unsigned long long u)
{
    float2 f;
    asm("mov.b64 {%0, %1}, %2;" : "=f"(f.x), "=f"(f.y) : "l"(u));
    return f;
}
__device__ __forceinline__ float sigf(float x) { return 1.f / (1.f + expf(-x)); }

// ---------------- warp MMA (baseline PTX; validated in round 9) ---------------
__device__ __forceinline__ void mma16816(float* d, const unsigned* a,
                                         const unsigned* b)
{
    asm volatile(
        "mma.sync.aligned.m16n8k16.row.col.f32.bf16.bf16.f32 "
        "{%0,%1,%2,%3}, {%4,%5,%6,%7}, {%8,%9}, {%0,%1,%2,%3};"
        : "+f"(d[0]), "+f"(d[1]), "+f"(d[2]), "+f"(d[3])
        : "r"(a[0]), "r"(a[1]), "r"(a[2]), "r"(a[3]), "r"(b[0]), "r"(b[1]));
}

// =============================================================================
// Tiled fp32 GEMM (f32x2) — used ONLY for layer 0 (K=41).
// =============================================================================
__global__ __launch_bounds__(256, 2)
void gemm_gates(const float* __restrict__ A, const float* __restrict__ B,
                const float* __restrict__ bias1, const float* __restrict__ bias2,
                float* __restrict__ Gout, int K, int ldb, int amode)
{
    __shared__ float As[16][128];
    __shared__ float Bs[16][128];
    int tid  = threadIdx.x;
    int row0 = blockIdx.y * 128;
    int col0 = blockIdx.x * 128;
    int tx = tid & 15, ty = tid >> 4;

    unsigned long long acc2[8][4];
#pragma unroll
    for (int m = 0; m < 8; m++)
#pragma unroll
        for (int n = 0; n < 4; n++) acc2[m][n] = 0ull;

    for (int kt = 0; kt < K; kt += 16) {
#pragma unroll
        for (int ii = 0; ii < 8; ii++) {
            int i = tid + 256 * ii;
            int kk = i >> 7, r = i & 127;
            int row = row0 + r;
            int k = kt + kk;
            float v = 0.f;
            if (k < K) {
                if (amode == 0) v = A[(row & 31) * (LSEQ * DIN) + (row >> 5) * DIN + k];
                else            v = A[(row >> 5) * (H2 * BATCH) + k * BATCH + (row & 31)];
            }
            As[kk][r] = v;
        }
#pragma unroll
        for (int ii = 0; ii < 8; ii++) {
            int i = tid + 256 * ii;
            int c = i >> 4, kk = i & 15;
            int k = kt + kk;
            Bs[kk][c] = (k < K) ? B[(col0 + c) * ldb + k] : 0.f;
        }
        __syncthreads();
#pragma unroll
        for (int kk = 0; kk < 16; kk++) {
            float a[8];
            *(float4*)&a[0] = *(const float4*)&As[kk][ty * 8];
            *(float4*)&a[4] = *(const float4*)&As[kk][ty * 8 + 4];
            ulonglong2 b01 = *(const ulonglong2*)&Bs[kk][tx * 8];
            ulonglong2 b23 = *(const ulonglong2*)&Bs[kk][tx * 8 + 4];
            unsigned long long bp[4] = { b01.x, b01.y, b23.x, b23.y };
#pragma unroll
            for (int m = 0; m < 8; m++) {
                unsigned long long am = dupf(a[m]);
#pragma unroll
                for (int n = 0; n < 4; n++) ffma2(acc2[m][n], am, bp[n]);
            }
        }
        __syncthreads();
    }

#pragma unroll
    for (int m = 0; m < 8; m++) {
        int row = row0 + ty * 8 + m;
        int t = row >> 5, b = row & 31;
#pragma unroll
        for (int n = 0; n < 4; n++) {
            float2 v = unpackf(acc2[m][n]);
            int c0 = col0 + tx * 8 + 2 * n;
#pragma unroll
            for (int q = 0; q < 2; q++) {
                int col = c0 + q;
                int dir = (col >= GATES) ? 1 : 0;
                int j = col - dir * GATES;
                float val = (q == 0 ? v.x : v.y) + bias1[col] + bias2[col];
                Gout[((dir * LSEQ + t) * GATES + j) * BATCH + b] = val;
            }
        }
    }
}

// =============================================================================
// conv_w: Wih1 [6400][1600] f32 -> Bhi/Blo packed bf16 pairs [6400][800].
// =============================================================================
__global__ __launch_bounds__(256)
void conv_w(const float* __restrict__ W)
{
    long i = (long)blockIdx.x * 256 + threadIdx.x;
    if (i >= 6400L * 800) return;
    float2 v = *(const float2*)(W + 2 * i);
    unsigned hi, lo;
    split2(v.x, v.y, hi, lo);
    g_Bhi[i] = hi;
    g_Blo[i] = lo;
}

// =============================================================================
// conv_h: h0 [t][k][b] f32 -> Ahi/Alo [row=t*32+b][k/2] packed bf16 pairs.
// =============================================================================
__global__ __launch_bounds__(256)
void conv_h(void)
{
    __shared__ float hsm[320 * 32];
    int t = blockIdx.x;
    int tid = threadIdx.x;
    const float* src = g_h0 + (long)t * (H2 * BATCH);
    for (int slab = 0; slab < 5; slab++) {
        __syncthreads();
#pragma unroll
        for (int i = 0; i < 40; i++)
            hsm[tid + 256 * i] = src[slab * (320 * 32) + tid + 256 * i];
        __syncthreads();
        for (int i = tid; i < 32 * 160; i += 256) {
            int b = i / 160, kp = i - b * 160;
            float v0 = hsm[(2 * kp) * 32 + b];
            float v1 = hsm[(2 * kp + 1) * 32 + b];
            unsigned hi, lo;
            split2(v0, v1, hi, lo);
            long o = (long)(t * 32 + b) * 800 + slab * 160 + kp;
            g_Ahi[o] = hi;
            g_Alo[o] = lo;
        }
    }
}

// =============================================================================
// gemm1_mma: G1 = h0 @ Wih1^T + biases via bf16-split warp MMA (m16n8k16).
// (unchanged from passing round 9)
// =============================================================================
#define MM_STRIDE 36
#define MM_ASZ (128 * MM_STRIDE)
#define MM_SMEM (4 * MM_ASZ * 4)                    // 73728 bytes

__global__ __launch_bounds__(256, 2)
void gemm1_mma(const float* __restrict__ bias1, const float* __restrict__ bias2,
               float* __restrict__ Gout)
{
    extern __shared__ unsigned sm[];
    unsigned* Ah = sm;
    unsigned* Al = Ah + MM_ASZ;
    unsigned* Bh = Al + MM_ASZ;
    unsigned* Bl = Bh + MM_ASZ;

    int tid = threadIdx.x;
    int wid = tid >> 5, lane = tid & 31;
    int g = lane >> 2, tig = lane & 3;
    int col0 = blockIdx.x * 128;
    int row0 = blockIdx.y * 128;
    int m0 = (wid & 3) * 32;
    int n0 = (wid >> 2) * 64;

    float acc[2][8][4];
#pragma unroll
    for (int mt = 0; mt < 2; mt++)
#pragma unroll
        for (int nt = 0; nt < 8; nt++)
#pragma unroll
            for (int q = 0; q < 4; q++) acc[mt][nt][q] = 0.f;

    int sr = tid >> 4, skq = tid & 15;

    for (int ch = 0; ch < 25; ch++) {
        __syncthreads();
#pragma unroll
        for (int it = 0; it < 8; it++) {
            int rr = sr + it * 16;
            long ao = (long)(row0 + rr) * 800 + ch * 32 + 2 * skq;
            long bo = (long)(col0 + rr) * 800 + ch * 32 + 2 * skq;
            *(uint2*)(Ah + rr * MM_STRIDE + 2 * skq) = *(const uint2*)(g_Ahi + ao);
            *(uint2*)(Al + rr * MM_STRIDE + 2 * skq) = *(const uint2*)(g_Alo + ao);
            *(uint2*)(Bh + rr * MM_STRIDE + 2 * skq) = *(const uint2*)(g_Bhi + bo);
            *(uint2*)(Bl + rr * MM_STRIDE + 2 * skq) = *(const uint2*)(g_Blo + bo);
        }
        __syncthreads();

#pragma unroll
        for (int kk = 0; kk < 4; kk++) {
            int kpb = kk * 8;
            unsigned bh[8][2], bl[8][2];
#pragma unroll
            for (int nt = 0; nt < 8; nt++) {
                int br = (n0 + nt * 8 + g) * MM_STRIDE + kpb + tig;
                bh[nt][0] = Bh[br];     bh[nt][1] = Bh[br + 4];
                bl[nt][0] = Bl[br];     bl[nt][1] = Bl[br + 4];
            }
#pragma unroll
            for (int mt = 0; mt < 2; mt++) {
                int ar0 = (m0 + mt * 16 + g) * MM_STRIDE + kpb + tig;
                int ar1 = ar0 + 8 * MM_STRIDE;
                unsigned ah[4] = { Ah[ar0], Ah[ar1], Ah[ar0 + 4], Ah[ar1 + 4] };
                unsigned al[4] = { Al[ar0], Al[ar1], Al[ar0 + 4], Al[ar1 + 4] };
#pragma unroll
                for (int nt = 0; nt < 8; nt++) {
                    mma16816(acc[mt][nt], ah, bh[nt]);
                    mma16816(acc[mt][nt], ah, bl[nt]);
                    mma16816(acc[mt][nt], al, bh[nt]);
                }
            }
        }
    }

#pragma unroll
    for (int mt = 0; mt < 2; mt++) {
        int r0 = row0 + m0 + mt * 16 + g;
        int r1 = r0 + 8;
        int t0 = r0 >> 5, b0 = r0 & 31;
        int t1 = r1 >> 5, b1 = r1 & 31;
#pragma unroll
        for (int nt = 0; nt < 8; nt++) {
            int c0 = col0 + n0 + nt * 8 + 2 * tig;
#pragma unroll
            for (int q = 0; q < 2; q++) {
                int col = c0 + q;
                int dir = (col >= GATES) ? 1 : 0;
                int j = col - dir * GATES;
                float bb = bias1[col] + bias2[col];
                Gout[((long)(dir * LSEQ + t0) * GATES + j) * BATCH + b0] =
                    acc[mt][nt][q] + bb;
                Gout[((long)(dir * LSEQ + t1) * GATES + j) * BATCH + b1] =
                    acc[mt][nt][2 + q] + bb;
            }
        }
    }
}

// =============================================================================
// Persistent bidirectional LSTM recurrence — MMA inner matvec (FIXED mapping).
// Grid 100 CTAs x 256 threads = 8 warps. Warp w: gate = w&3, k-half = w>>2.
// Rows = gate*16 + unit (64 rows); each warp MMAs its 400-k half (5 of the
// 10 k16 iterations per 160-k chunk), 4 n8 tiles over batch, 3 split passes.
// Partials -> pb[khalf][64][32] (16KB, overlaps h-staging region); cell phase
// sums the halves. Weight smem rows <=63, kp <=399 (stride 404); h rows <=31,
// kp <=83 (stride 84) — all in-bounds (R10 crash was wid-up-to-7 row overrun).
// =============================================================================
#define NCTA_DIR 50
#define WSTR 404
#define BSTR 84
#define LS_WW (64 * WSTR)                     // words per weight buffer
#define LS_B_OFF (2 * LS_WW * 4)              // 206848 bytes
#define LS_BW (32 * BSTR)                     // words per h buffer
#define SMEM_LSTM (LS_B_OFF + 2 * LS_BW * 4)  // 228352 bytes

__global__ __launch_bounds__(256, 1)
void lstm_persist(const float* __restrict__ Whh, int layer)
{
    extern __shared__ char smemc[];
    unsigned* wsH = (unsigned*)smemc;                  // [64][WSTR]
    unsigned* wsL = wsH + LS_WW;
    unsigned* bsH = (unsigned*)(smemc + LS_B_OFF);     // [32][BSTR]
    unsigned* bsL = bsH + LS_BW;
    float* pb = (float*)(smemc + LS_B_OFF);            // [2][64][32] overlaps bs

    const float* G = layer ? g_G1 : g_G0;
    float* hout    = layer ? g_h1 : g_h0;

    int c   = blockIdx.x;
    int dir = c / NCTA_DIR;
    int ubase = (c % NCTA_DIR) * 16;
    int tid = threadIdx.x;
    int wid = tid >> 5, lane = tid & 31;
    int gate  = wid & 3;          // MMA gate for this warp
    int khalf = wid >> 2;         // k-half 0/1
    int g = lane >> 2, tig = lane & 3;
    // cell mapping: thread -> (unit pair 2*ul, batch cb)
    int cb = tid & 31, ul = tid >> 5;
    int u0 = ubase + 2 * ul;

    unsigned* hbH = g_hbf_hi + dir * 32 * 400;         // [32][400]
    unsigned* hbL = g_hbf_lo + dir * 32 * 400;

    unsigned* cnt = &g_cnt[layer * 2 + dir];
    unsigned* ack = &g_ack[layer * 2 + dir];

    // ---- convert Whh slice -> smem bf16 hi/lo (once) ----
    const float* Wd = Whh + (long)dir * GATES * HID;
    for (int i = tid; i < 64 * 400; i += 256) {
        int r = i / 400, kp = i % 400;
        int grow = (r >> 4) * HID + ubase + (r & 15);
        float v0 = Wd[(long)grow * HID + 2 * kp];
        float v1 = Wd[(long)grow * HID + 2 * kp + 1];
        unsigned hi, lo;
        split2(v0, v1, hi, lo);
        wsH[r * WSTR + kp] = hi;
        wsL[r * WSTR + kp] = lo;
    }
    __syncthreads();

    float c0r = 0.f, c1r = 0.f;

    for (int s = 0; s < LSEQ; s++) {
        int t = dir ? (LSEQ - 1 - s) : s;

        // gate pre-activations (cell mapping), issued early
        long gb = ((long)(dir * LSEQ + t)) * GATES * BATCH;
        float gp[4][2];
#pragma unroll
        for (int g4 = 0; g4 < 4; g4++) {
            gp[g4][0] = G[gb + (long)(g4 * HID + u0) * BATCH + cb];
            gp[g4][1] = G[gb + (long)(g4 * HID + u0 + 1) * BATCH + cb];
        }

        float ds[4][2] = {{0.f,0.f},{0.f,0.f},{0.f,0.f},{0.f,0.f}};

        if (s > 0) {
            float acc[4][4];
#pragma unroll
            for (int nt = 0; nt < 4; nt++)
#pragma unroll
                for (int q = 0; q < 4; q++) acc[nt][q] = 0.f;

            for (int ch = 0; ch < 5; ch++) {
                __syncthreads();                       // bs free
                for (int i = tid; i < 2560; i += 256) {
                    int b = i / 80, kp = i - b * 80;
                    bsH[b * BSTR + kp] = __ldcg(hbH + b * 400 + ch * 80 + kp);
                    bsL[b * BSTR + kp] = __ldcg(hbL + b * 400 + ch * 80 + kp);
                }
                __syncthreads();                       // bs ready
                // warp does its k-half: kk in [khalf*5, khalf*5+5)
#pragma unroll
                for (int ki = 0; ki < 5; ki++) {
                    int kk = khalf * 5 + ki;
                    int akp = ch * 80 + kk * 8 + tig;
                    int ar0 = (gate * 16 + g) * WSTR + akp;
                    int ar1 = ar0 + 8 * WSTR;
                    unsigned ah[4] = { wsH[ar0], wsH[ar1], wsH[ar0+4], wsH[ar1+4] };
                    unsigned al[4] = { wsL[ar0], wsL[ar1], wsL[ar0+4], wsL[ar1+4] };
                    int bkp = kk * 8 + tig;
#pragma unroll
                    for (int nt = 0; nt < 4; nt++) {
                        int br = (nt * 8 + g) * BSTR + bkp;
                        unsigned bh[2] = { bsH[br], bsH[br + 4] };
                        unsigned bl[2] = { bsL[br], bsL[br + 4] };
                        mma16816(acc[nt], ah, bh);
                        mma16816(acc[nt], ah, bl);
                        mma16816(acc[nt], al, bh);
                    }
                }
            }
            __syncthreads();                           // bs done -> pb reuse
            // publish per-half partials: pb[khalf][gate*16+unit][batch]
            {
                float* pbW = pb + khalf * (64 * 32);
#pragma unroll
                for (int nt = 0; nt < 4; nt++) {
                    int colb = nt * 8 + 2 * tig;
                    pbW[(gate * 16 + g) * 32 + colb]         = acc[nt][0];
                    pbW[(gate * 16 + g) * 32 + colb + 1]     = acc[nt][1];
                    pbW[(gate * 16 + g + 8) * 32 + colb]     = acc[nt][2];
                    pbW[(gate * 16 + g + 8) * 32 + colb + 1] = acc[nt][3];
                }
            }
            __syncthreads();
#pragma unroll
            for (int g4 = 0; g4 < 4; g4++) {
                int r0 = (g4 * 16 + 2 * ul) * 32 + cb;
                int r1 = (g4 * 16 + 2 * ul + 1) * 32 + cb;
                ds[g4][0] = pb[r0] + pb[64 * 32 + r0];
                ds[g4][1] = pb[r1] + pb[64 * 32 + r1];
            }
            __syncthreads();                           // pb read before next overwrite
        }

        // ---- LSTM cell (two units) ----
        float ai0 = gp[0][0] + ds[0][0], ai1 = gp[0][1] + ds[0][1];
        float af0 = gp[1][0] + ds[1][0], af1 = gp[1][1] + ds[1][1];
        float ag0 = gp[2][0] + ds[2][0], ag1 = gp[2][1] + ds[2][1];
        float ao0 = gp[3][0] + ds[3][0], ao1 = gp[3][1] + ds[3][1];

        c0r = sigf(af0) * c0r + sigf(ai0) * tanhf(ag0);
        c1r = sigf(af1) * c1r + sigf(ai1) * tanhf(ag1);
        float h0v = sigf(ao0) * tanhf(c0r);
        float h1v = sigf(ao1) * tanhf(c1r);

        long hix = ((long)t * H2 + dir * HID + u0) * BATCH + cb;
        __stcg(hout + hix, h0v);
        __stcg(hout + hix + BATCH, h1v);

        // bf16 hi/lo h for next step's MMA (packed index = u0/2)
        unsigned hhi, hlo;
        split2(h0v, h1v, hhi, hlo);
        __stcg(hbH + cb * 400 + (u0 >> 1), hhi);
        __stcg(hbL + cb * 400 + (u0 >> 1), hlo);

        // ---- grid barrier over this direction's 50 CTAs ----
        __syncthreads();
        if (tid == 0) {
            asm volatile("red.release.gpu.global.add.u32 [%0], %1;"
                         :: "l"(cnt), "r"(1u) : "memory");
            unsigned target = (unsigned)(s + 1) * NCTA_DIR;
            unsigned v;
            do {
                asm volatile("ld.acquire.gpu.global.u32 %0, [%1];"
                             : "=r"(v) : "l"(cnt) : "memory");
            } while (v < target);
        }
        __syncthreads();
    }

    // ---- replay-safe counter reset via ack ----
    if (tid == 0) {
        asm volatile("red.release.gpu.global.add.u32 [%0], %1;"
                     :: "l"(ack), "r"(1u) : "memory");
        if ((c % NCTA_DIR) == 0) {
            unsigned v;
            do {
                asm volatile("ld.acquire.gpu.global.u32 %0, [%1];"
                             : "=r"(v) : "l"(ack) : "memory");
            } while (v < NCTA_DIR);
            *cnt = 0;
            *ack = 0;
            __threadfence();
        }
    }
}

// =============================================================================
// Fused head (k-chunk 160): linear -> softmax over BATCH dim -> angles.
// =============================================================================
#define HCHUNK 160
__global__ __launch_bounds__(640)
void head_kernel(const float* __restrict__ wlin, const float* __restrict__ blin,
                 const float* __restrict__ alphabet)
{
    int l = blockIdx.x;
    int tid = threadIdx.x;
    int j = tid >> 5, b = tid & 31;

    __shared__ float hs[HCHUNK * 32];
    __shared__ float ps[20][32];
    __shared__ float sa[60], ca[60];

    if (tid < 60) { float v = alphabet[tid]; sa[tid] = sinf(v); ca[tid] = cosf(v); }

    float acc = blin[j];
    const float* hb = g_h1 + (long)l * (H2 * BATCH);
    const float* w = wlin + j * H2;
    for (int k0 = 0; k0 < H2; k0 += HCHUNK) {
        __syncthreads();
#pragma unroll
        for (int i = 0; i < (HCHUNK * 32) / 640; i++)
            hs[tid + 640 * i] = hb[k0 * 32 + tid + 640 * i];
        __syncthreads();
#pragma unroll 8
        for (int k = 0; k < HCHUNK; k += 4) {
            float4 w4 = *(const float4*)(w + k0 + k);
            acc += w4.x * hs[(k + 0) * 32 + b];
            acc += w4.y * hs[(k + 1) * 32 + b];
            acc += w4.z * hs[(k + 2) * 32 + b];
            acc += w4.w * hs[(k + 3) * 32 + b];
        }
    }
    float m = acc;
#pragma unroll
    for (int o = 16; o; o >>= 1) m = fmaxf(m, __shfl_xor_sync(0xffffffffu, m, o));
    float e = expf(acc - m);
    float ssum = e;
#pragma unroll
    for (int o = 16; o; o >>= 1) ssum += __shfl_xor_sync(0xffffffffu, ssum, o);
    ps[j][b] = e / ssum;
    __syncthreads();

    if (tid < 96) {
        int b2 = tid / 3, i = tid - b2 * 3;
        float ssin = 0.f, scos = 0.f;
#pragma unroll
        for (int jj = 0; jj < 20; jj++) {
            float p = ps[jj][b2];
            ssin += p * sa[jj * 3 + i];
            scos += p * ca[jj * 3 + i];
        }
        g_ang[l * 96 + b2 * 3 + i] = atan2f(ssin, scos);
    }
}

// =============================================================================
// NeRF backbone extension (unchanged).
// =============================================================================
__global__ void nerf_kernel(float* __restrict__ out)
{
    int b = threadIdx.x;
    float ax = 0.f,   ay = 0.f,   az = 0.f;
    float bx = 100.f, by = 0.f,   bz = 0.f;
    float cx = 200.f, cy = 100.f, cz = 0.f;

    const float BL0 = 145.801f, BL1 = 152.326f, BL2 = 132.868f;
    const float TH0 = 2.124f,   TH1 = 1.941f,   TH2 = 2.028f;
    float d0a = -BL0 * cosf(TH0), d1a = BL0 * sinf(TH0);
    float d0b = -BL1 * cosf(TH1), d1b = BL1 * sinf(TH1);
    float d0c = -BL2 * cosf(TH2), d1c = BL2 * sinf(TH2);

    for (int s = 0; s < NCOORD; s++) {
        float phi = g_ang[s * 32 + b];
        int m = s - (s / 3) * 3;
        float d0 = (m == 0) ? d0a : (m == 1) ? d0b : d0c;
        float rs = (m == 0) ? d1a : (m == 1) ? d1b : d1c;

        float vx = cx - bx, vy = cy - by, vz = cz - bz;
        float inv = 1.f / (sqrtf(vx * vx + vy * vy + vz * vz) + 1e-12f);
        float bcx = vx * inv, bcy = vy * inv, bcz = vz * inv;

        float ux = bx - ax, uy = by - ay, uz = bz - az;
        float nx = uy * bcz - uz * bcy;
        float ny = uz * bcx - ux * bcz;
        float nz = ux * bcy - uy * bcx;
        float invn = 1.f / (sqrtf(nx * nx + ny * ny + nz * nz) + 1e-12f);
        nx *= invn; ny *= invn; nz *= invn;

        float mx = ny * bcz - nz * bcy;
        float my = nz * bcx - nx * bcz;
        float mz = nx * bcy - ny * bcx;

        float sp, cp;
        sincosf(phi, &sp, &cp);
        float d1 = rs * cp, d2 = rs * sp;

        float dx = cx + d0 * bcx + d1 * mx + d2 * nx;
        float dy = cy + d0 * bcy + d1 * my + d2 * ny;
        float dz = cz + d0 * bcz + d1 * mz + d2 * nz;

        out[s * 96 + b * 3 + 0] = dx;
        out[s * 96 + b * 3 + 1] = dy;
        out[s * 96 + b * 3 + 2] = dz;

        ax = bx; ay = by; az = bz;
        bx = cx; by = cy; bz = cz;
        cx = dx; cy = dy; cz = dz;
    }
}

// =============================================================================
extern "C" void kernel_launch(void* const* d_in, const int* in_sizes, int n_in,
                              void* d_out, int out_size)
{
    const float* x     = (const float*)d_in[0];
    const float* wih0  = (const float*)d_in[1];
    const float* whh0  = (const float*)d_in[2];
    const float* bih0  = (const float*)d_in[3];
    const float* bhh0  = (const float*)d_in[4];
    const float* wih1  = (const float*)d_in[5];
    const float* whh1  = (const float*)d_in[6];
    const float* bih1  = (const float*)d_in[7];
    const float* bhh1  = (const float*)d_in[8];
    const float* wlin  = (const float*)d_in[9];
    const float* blin  = (const float*)d_in[10];
    const float* alpha = (const float*)d_in[11];
    float* out = (float*)d_out;

    static int attr_done = 0;
    if (!attr_done) {
        cudaFuncSetAttribute(lstm_persist,
                             cudaFuncAttributeMaxDynamicSharedMemorySize, SMEM_LSTM);
        cudaFuncSetAttribute(gemm1_mma,
                             cudaFuncAttributeMaxDynamicSharedMemorySize, MM_SMEM);
        attr_done = 1;
    }

    float* G0p; cudaGetSymbolAddress((void**)&G0p, g_G0);
    float* G1p; cudaGetSymbolAddress((void**)&G1p, g_G1);

    // Layer 0 input-side pre-activations: G0 = x @ Wih0^T + biases (fp32, K=41)
    gemm_gates<<<dim3(50, 175), 256>>>(x, wih0, bih0, bhh0, G0p, DIN, DIN, 0);

    // Weight conversion for layer-1 GEMM (independent of lstm0)
    conv_w<<<20000, 256>>>(wih1);

    // Layer 0 recurrence (MMA inner matvec)
    lstm_persist<<<100, 256, SMEM_LSTM>>>(whh0, 0);

    // h0 -> bf16 hi/lo row-major
    conv_h<<<LSEQ, 256>>>();

    // Layer 1 input-side pre-activations via bf16-split warp MMA
    gemm1_mma<<<dim3(50, 175), 256, MM_SMEM>>>(bih1, bhh1, G1p);

    // Layer 1 recurrence
    lstm_persist<<<100, 256, SMEM_LSTM>>>(whh1, 1);

    // Head: linear -> softmax(batch dim) -> angles
    head_kernel<<<LSEQ, 640>>>(wlin, blin, alpha);

    // NeRF extension -> output coords [2100][32][3]
    nerf_kernel<<<1, 32>>>(out);
}

// round 12
// speedup vs baseline: 6.5241x; 1.1533x over previous
#include <cuda_runtime.h>
#include <cuda_bf16.h>
#include <cuda_fp16.h>
#include <math.h>
#include <stdint.h>

// Problem constants
#define LSEQ 700
#define BATCH 32
#define DIN 41
#define HID 800
#define GATES 3200          // 4*HID
#define H2 1600             // 2*HID
#define NCOORD 2100         // 3*LSEQ

// ---------------- device scratch (allocation-free rule: __device__ globals) ---
__device__ float g_G0[2L * LSEQ * GATES * BATCH];   // [2][700][3200][32]
__device__ float g_G1[2L * LSEQ * GATES * BATCH];
__device__ float g_h0[LSEQ * H2 * BATCH];           // [700][1600][32]
__device__ float g_h1[LSEQ * H2 * BATCH];
__device__ float g_ang[LSEQ * BATCH * 3];
__device__ unsigned g_cnt[4];
__device__ unsigned g_ack[4];
// fp16 operands for layer-1 input GEMM (uint32 = 2 packed fp16)
__device__ unsigned g_Ahi[22400 * 800];             // h0 single fp16 [row][k/2]
__device__ unsigned g_Bhi[6400 * 800];              // Wih1 hi [col][k/2]
__device__ unsigned g_Blo[6400 * 800];              // Wih1 lo (residual)
// fp16 h state for recurrence MMA: [dir][batch][k/2]
__device__ unsigned g_hbf[2 * 32 * 400];

// ---------------- fp16 pack/split helpers -------------------------------------
__device__ __forceinline__ unsigned packh2(float a, float b)
{
    __half2 h = __floats2half2_rn(a, b);
    return *(unsigned*)&h;
}
__device__ __forceinline__ void splith2(float a, float b,
                                        unsigned& hi, unsigned& lo)
{
    __half ha = __float2half_rn(a), hb2 = __float2half_rn(b);
    __half la = __float2half_rn(a - __half2float(ha));
    __half lb = __float2half_rn(b - __half2float(hb2));
    hi = ((unsigned)__half_as_ushort(hb2) << 16) | __half_as_ushort(ha);
    lo = ((unsigned)__half_as_ushort(lb) << 16) | __half_as_ushort(la);
}

// ---------------- packed fp32x2 helpers --------------------------------------
__device__ __forceinline__ void ffma2(unsigned long long& d,
                                      unsigned long long a,
                                      unsigned long long b)
{
    asm("fma.rn.f32x2 %0, %1, %2, %3;" : "=l"(d) : "l"(a), "l"(b), "l"(d));
}
__device__ __forceinline__ unsigned long long dupf(float x)
{
    unsigned long long r;
    asm("mov.b64 %0, {%1, %1};" : "=l"(r) : "f"(x));
    return r;
}
__device__ __forceinline__ float2 unpackf(unsigned long long u)
{
    float2 f;
    asm("mov.b64 {%0, %1}, %2;" : "=f"(f.x), "=f"(f.y) : "l"(u));
    return f;
}
__device__ __forceinline__ float sigf(float x) { return 1.f / (1.f + expf(-x)); }

// ---------------- warp MMA fp16 (baseline PTX; fragment layout == bf16) -------
__device__ __forceinline__ void mma16816h(float* d, const unsigned* a,
                                          const unsigned* b)
{
    asm volatile(
        "mma.sync.aligned.m16n8k16.row.col.f32.f16.f16.f32 "
        "{%0,%1,%2,%3}, {%4,%5,%6,%7}, {%8,%9}, {%0,%1,%2,%3};"
        : "+f"(d[0]), "+f"(d[1]), "+f"(d[2]), "+f"(d[3])
        : "r"(a[0]), "r"(a[1]), "r"(a[2]), "r"(a[3]), "r"(b[0]), "r"(b[1]));
}

// =============================================================================
// Tiled fp32 GEMM (f32x2) — used ONLY for layer 0 (K=41).
// =============================================================================
__global__ __launch_bounds__(256, 2)
void gemm_gates(const float* __restrict__ A, const float* __restrict__ B,
                const float* __restrict__ bias1, const float* __restrict__ bias2,
                float* __restrict__ Gout, int K, int ldb, int amode)
{
    __shared__ float As[16][128];
    __shared__ float Bs[16][128];
    int tid  = threadIdx.x;
    int row0 = blockIdx.y * 128;
    int col0 = blockIdx.x * 128;
    int tx = tid & 15, ty = tid >> 4;

    unsigned long long acc2[8][4];
#pragma unroll
    for (int m = 0; m < 8; m++)
#pragma unroll
        for (int n = 0; n < 4; n++) acc2[m][n] = 0ull;

    for (int kt = 0; kt < K; kt += 16) {
#pragma unroll
        for (int ii = 0; ii < 8; ii++) {
            int i = tid + 256 * ii;
            int kk = i >> 7, r = i & 127;
            int row = row0 + r;
            int k = kt + kk;
            float v = 0.f;
            if (k < K) {
                if (amode == 0) v = A[(row & 31) * (LSEQ * DIN) + (row >> 5) * DIN + k];
                else            v = A[(row >> 5) * (H2 * BATCH) + k * BATCH + (row & 31)];
            }
            As[kk][r] = v;
        }
#pragma unroll
        for (int ii = 0; ii < 8; ii++) {
            int i = tid + 256 * ii;
            int c = i >> 4, kk = i & 15;
            int k = kt + kk;
            Bs[kk][c] = (k < K) ? B[(col0 + c) * ldb + k] : 0.f;
        }
        __syncthreads();
#pragma unroll
        for (int kk = 0; kk < 16; kk++) {
            float a[8];
            *(float4*)&a[0] = *(const float4*)&As[kk][ty * 8];
            *(float4*)&a[4] = *(const float4*)&As[kk][ty * 8 + 4];
            ulonglong2 b01 = *(const ulonglong2*)&Bs[kk][tx * 8];
            ulonglong2 b23 = *(const ulonglong2*)&Bs[kk][tx * 8 + 4];
            unsigned long long bp[4] = { b01.x, b01.y, b23.x, b23.y };
#pragma unroll
            for (int m = 0; m < 8; m++) {
                unsigned long long am = dupf(a[m]);
#pragma unroll
                for (int n = 0; n < 4; n++) ffma2(acc2[m][n], am, bp[n]);
            }
        }
        __syncthreads();
    }

#pragma unroll
    for (int m = 0; m < 8; m++) {
        int row = row0 + ty * 8 + m;
        int t = row >> 5, b = row & 31;
#pragma unroll
        for (int n = 0; n < 4; n++) {
            float2 v = unpackf(acc2[m][n]);
            int c0 = col0 + tx * 8 + 2 * n;
#pragma unroll
            for (int q = 0; q < 2; q++) {
                int col = c0 + q;
                int dir = (col >= GATES) ? 1 : 0;
                int j = col - dir * GATES;
                float val = (q == 0 ? v.x : v.y) + bias1[col] + bias2[col];
                Gout[((dir * LSEQ + t) * GATES + j) * BATCH + b] = val;
            }
        }
    }
}

// =============================================================================
// conv_w: Wih1 [6400][1600] f32 -> fp16 hi/lo packed pairs [6400][800].
// =============================================================================
__global__ __launch_bounds__(256)
void conv_w(const float* __restrict__ W)
{
    long i = (long)blockIdx.x * 256 + threadIdx.x;
    if (i >= 6400L * 800) return;
    float2 v = *(const float2*)(W + 2 * i);
    unsigned hi, lo;
    splith2(v.x, v.y, hi, lo);
    g_Bhi[i] = hi;
    g_Blo[i] = lo;
}

// =============================================================================
// conv_h: h0 [t][k][b] f32 -> single fp16 packed pairs [row=t*32+b][k/2].
// =============================================================================
__global__ __launch_bounds__(256)
void conv_h(void)
{
    __shared__ float hsm[320 * 32];
    int t = blockIdx.x;
    int tid = threadIdx.x;
    const float* src = g_h0 + (long)t * (H2 * BATCH);
    for (int slab = 0; slab < 5; slab++) {
        __syncthreads();
#pragma unroll
        for (int i = 0; i < 40; i++)
            hsm[tid + 256 * i] = src[slab * (320 * 32) + tid + 256 * i];
        __syncthreads();
        for (int i = tid; i < 32 * 160; i += 256) {
            int b = i / 160, kp = i - b * 160;
            float v0 = hsm[(2 * kp) * 32 + b];
            float v1 = hsm[(2 * kp + 1) * 32 + b];
            long o = (long)(t * 32 + b) * 800 + slab * 160 + kp;
            g_Ahi[o] = packh2(v0, v1);
        }
    }
}

// =============================================================================
// gemm1_mma: G1 = h0 @ Wih1^T + biases via fp16 warp MMA, 2 passes:
//   D = h * Whi + h * Wlo  (W-side split; h single fp16).
// Grid (50 col-tiles x 175 row-tiles), 256 threads = 8 warps.
// =============================================================================
#define MM_STRIDE 36
#define MM_ASZ (128 * MM_STRIDE)
#define MM_SMEM (3 * MM_ASZ * 4)                    // 55296 bytes

__global__ __launch_bounds__(256, 2)
void gemm1_mma(const float* __restrict__ bias1, const float* __restrict__ bias2,
               float* __restrict__ Gout)
{
    extern __shared__ unsigned sm[];
    unsigned* Ah = sm;
    unsigned* Bh = Ah + MM_ASZ;
    unsigned* Bl = Bh + MM_ASZ;

    int tid = threadIdx.x;
    int wid = tid >> 5, lane = tid & 31;
    int g = lane >> 2, tig = lane & 3;
    int col0 = blockIdx.x * 128;
    int row0 = blockIdx.y * 128;
    int m0 = (wid & 3) * 32;
    int n0 = (wid >> 2) * 64;

    float acc[2][8][4];
#pragma unroll
    for (int mt = 0; mt < 2; mt++)
#pragma unroll
        for (int nt = 0; nt < 8; nt++)
#pragma unroll
            for (int q = 0; q < 4; q++) acc[mt][nt][q] = 0.f;

    int sr = tid >> 4, skq = tid & 15;

    for (int ch = 0; ch < 25; ch++) {
        __syncthreads();
#pragma unroll
        for (int it = 0; it < 8; it++) {
            int rr = sr + it * 16;
            long ao = (long)(row0 + rr) * 800 + ch * 32 + 2 * skq;
            long bo = (long)(col0 + rr) * 800 + ch * 32 + 2 * skq;
            *(uint2*)(Ah + rr * MM_STRIDE + 2 * skq) = *(const uint2*)(g_Ahi + ao);
            *(uint2*)(Bh + rr * MM_STRIDE + 2 * skq) = *(const uint2*)(g_Bhi + bo);
            *(uint2*)(Bl + rr * MM_STRIDE + 2 * skq) = *(const uint2*)(g_Blo + bo);
        }
        __syncthreads();

#pragma unroll
        for (int kk = 0; kk < 4; kk++) {
            int kpb = kk * 8;
            unsigned bh[8][2], bl[8][2];
#pragma unroll
            for (int nt = 0; nt < 8; nt++) {
                int br = (n0 + nt * 8 + g) * MM_STRIDE + kpb + tig;
                bh[nt][0] = Bh[br];     bh[nt][1] = Bh[br + 4];
                bl[nt][0] = Bl[br];     bl[nt][1] = Bl[br + 4];
            }
#pragma unroll
            for (int mt = 0; mt < 2; mt++) {
                int ar0 = (m0 + mt * 16 + g) * MM_STRIDE + kpb + tig;
                int ar1 = ar0 + 8 * MM_STRIDE;
                unsigned ah[4] = { Ah[ar0], Ah[ar1], Ah[ar0 + 4], Ah[ar1 + 4] };
#pragma unroll
                for (int nt = 0; nt < 8; nt++) {
                    mma16816h(acc[mt][nt], ah, bh[nt]);
                    mma16816h(acc[mt][nt], ah, bl[nt]);
                }
            }
        }
    }

#pragma unroll
    for (int mt = 0; mt < 2; mt++) {
        int r0 = row0 + m0 + mt * 16 + g;
        int r1 = r0 + 8;
        int t0 = r0 >> 5, b0 = r0 & 31;
        int t1 = r1 >> 5, b1 = r1 & 31;
#pragma unroll
        for (int nt = 0; nt < 8; nt++) {
            int c0 = col0 + n0 + nt * 8 + 2 * tig;
#pragma unroll
            for (int q = 0; q < 2; q++) {
                int col = c0 + q;
                int dir = (col >= GATES) ? 1 : 0;
                int j = col - dir * GATES;
                float bb = bias1[col] + bias2[col];
                Gout[((long)(dir * LSEQ + t0) * GATES + j) * BATCH + b0] =
                    acc[mt][nt][q] + bb;
                Gout[((long)(dir * LSEQ + t1) * GATES + j) * BATCH + b1] =
                    acc[mt][nt][2 + q] + bb;
            }
        }
    }
}

// =============================================================================
// Persistent bidirectional LSTM recurrence — fp16 MMA, 2 passes
//   (W split hi/lo fp16; h single fp16). Mapping as R11 (warp: gate=w&3,
//   khalf=w>>2). Weights smem fp16 hi/lo (206.8KB); h staged single-buffer
//   (10.75KB/chunk); pb[2][64][32] overlaps. All indices bounded as R11.
// =============================================================================
#define NCTA_DIR 50
#define WSTR 404
#define BSTR 84
#define LS_WW (64 * WSTR)                     // words per weight buffer
#define LS_B_OFF (2 * LS_WW * 4)              // 206848 bytes
#define SMEM_LSTM (LS_B_OFF + 2 * 64 * 32 * 4)  // + pb 16384 = 223232 bytes

__global__ __launch_bounds__(256, 1)
void lstm_persist(const float* __restrict__ Whh, int layer)
{
    extern __shared__ char smemc[];
    unsigned* wsH = (unsigned*)smemc;                  // [64][WSTR] fp16 hi pairs
    unsigned* wsL = wsH + LS_WW;                       // fp16 lo pairs
    unsigned* bs  = (unsigned*)(smemc + LS_B_OFF);     // [32][BSTR] fp16 h pairs
    float* pb = (float*)(smemc + LS_B_OFF);            // [2][64][32] overlaps bs

    const float* G = layer ? g_G1 : g_G0;
    float* hout    = layer ? g_h1 : g_h0;

    int c   = blockIdx.x;
    int dir = c / NCTA_DIR;
    int ubase = (c % NCTA_DIR) * 16;
    int tid = threadIdx.x;
    int wid = tid >> 5, lane = tid & 31;
    int gate  = wid & 3;          // MMA gate for this warp
    int khalf = wid >> 2;         // k-half 0/1
    int g = lane >> 2, tig = lane & 3;
    // cell mapping
    int cb = tid & 31, ul = tid >> 5;
    int u0 = ubase + 2 * ul;

    unsigned* hb = g_hbf + dir * 32 * 400;             // [32][400]

    unsigned* cnt = &g_cnt[layer * 2 + dir];
    unsigned* ack = &g_ack[layer * 2 + dir];

    // ---- convert Whh slice -> smem fp16 hi/lo (once) ----
    const float* Wd = Whh + (long)dir * GATES * HID;
    for (int i = tid; i < 64 * 400; i += 256) {
        int r = i / 400, kp = i % 400;
        int grow = (r >> 4) * HID + ubase + (r & 15);
        float v0 = Wd[(long)grow * HID + 2 * kp];
        float v1 = Wd[(long)grow * HID + 2 * kp + 1];
        unsigned hi, lo;
        splith2(v0, v1, hi, lo);
        wsH[r * WSTR + kp] = hi;
        wsL[r * WSTR + kp] = lo;
    }
    __syncthreads();

    float c0r = 0.f, c1r = 0.f;

    for (int s = 0; s < LSEQ; s++) {
        int t = dir ? (LSEQ - 1 - s) : s;

        // gate pre-activations (cell mapping), issued early
        long gb = ((long)(dir * LSEQ + t)) * GATES * BATCH;
        float gp[4][2];
#pragma unroll
        for (int g4 = 0; g4 < 4; g4++) {
            gp[g4][0] = G[gb + (long)(g4 * HID + u0) * BATCH + cb];
            gp[g4][1] = G[gb + (long)(g4 * HID + u0 + 1) * BATCH + cb];
        }

        float ds[4][2] = {{0.f,0.f},{0.f,0.f},{0.f,0.f},{0.f,0.f}};

        if (s > 0) {
            float acc[4][4];
#pragma unroll
            for (int nt = 0; nt < 4; nt++)
#pragma unroll
                for (int q = 0; q < 4; q++) acc[nt][q] = 0.f;

            for (int ch = 0; ch < 5; ch++) {
                __syncthreads();                       // bs free
                for (int i = tid; i < 2560; i += 256) {
                    int b = i / 80, kp = i - b * 80;
                    bs[b * BSTR + kp] = __ldcg(hb + b * 400 + ch * 80 + kp);
                }
                __syncthreads();                       // bs ready
#pragma unroll
                for (int ki = 0; ki < 5; ki++) {
                    int kk = khalf * 5 + ki;
                    int akp = ch * 80 + kk * 8 + tig;
                    int ar0 = (gate * 16 + g) * WSTR + akp;
                    int ar1 = ar0 + 8 * WSTR;
                    unsigned ah[4] = { wsH[ar0], wsH[ar1], wsH[ar0+4], wsH[ar1+4] };
                    unsigned al[4] = { wsL[ar0], wsL[ar1], wsL[ar0+4], wsL[ar1+4] };
                    int bkp = kk * 8 + tig;
#pragma unroll
                    for (int nt = 0; nt < 4; nt++) {
                        int br = (nt * 8 + g) * BSTR + bkp;
                        unsigned bfr[2] = { bs[br], bs[br + 4] };
                        mma16816h(acc[nt], ah, bfr);
                        mma16816h(acc[nt], al, bfr);
                    }
                }
            }
            __syncthreads();                           // bs done -> pb reuse
            {
                float* pbW = pb + khalf * (64 * 32);
#pragma unroll
                for (int nt = 0; nt < 4; nt++) {
                    int colb = nt * 8 + 2 * tig;
                    pbW[(gate * 16 + g) * 32 + colb]         = acc[nt][0];
                    pbW[(gate * 16 + g) * 32 + colb + 1]     = acc[nt][1];
                    pbW[(gate * 16 + g + 8) * 32 + colb]     = acc[nt][2];
                    pbW[(gate * 16 + g + 8) * 32 + colb + 1] = acc[nt][3];
                }
            }
            __syncthreads();
#pragma unroll
            for (int g4 = 0; g4 < 4; g4++) {
                int r0 = (g4 * 16 + 2 * ul) * 32 + cb;
                int r1 = (g4 * 16 + 2 * ul + 1) * 32 + cb;
                ds[g4][0] = pb[r0] + pb[64 * 32 + r0];
                ds[g4][1] = pb[r1] + pb[64 * 32 + r1];
            }
            __syncthreads();                           // pb read before overwrite
        }

        // ---- LSTM cell (two units) ----
        float ai0 = gp[0][0] + ds[0][0], ai1 = gp[0][1] + ds[0][1];
        float af0 = gp[1][0] + ds[1][0], af1 = gp[1][1] + ds[1][1];
        float ag0 = gp[2][0] + ds[2][0], ag1 = gp[2][1] + ds[2][1];
        float ao0 = gp[3][0] + ds[3][0], ao1 = gp[3][1] + ds[3][1];

        c0r = sigf(af0) * c0r + sigf(ai0) * tanhf(ag0);
        c1r = sigf(af1) * c1r + sigf(ai1) * tanhf(ag1);
        float h0v = sigf(ao0) * tanhf(c0r);
        float h1v = sigf(ao1) * tanhf(c1r);

        long hix = ((long)t * H2 + dir * HID + u0) * BATCH + cb;
        __stcg(hout + hix, h0v);
        __stcg(hout + hix + BATCH, h1v);

        // single fp16 packed h for next step's MMA
        __stcg(hb + cb * 400 + (u0 >> 1), packh2(h0v, h1v));

        // ---- grid barrier over this direction's 50 CTAs ----
        __syncthreads();
        if (tid == 0) {
            asm volatile("red.release.gpu.global.add.u32 [%0], %1;"
                         :: "l"(cnt), "r"(1u) : "memory");
            unsigned target = (unsigned)(s + 1) * NCTA_DIR;
            unsigned v;
            do {
                asm volatile("ld.acquire.gpu.global.u32 %0, [%1];"
                             : "=r"(v) : "l"(cnt) : "memory");
            } while (v < target);
        }
        __syncthreads();
    }

    // ---- replay-safe counter reset via ack ----
    if (tid == 0) {
        asm volatile("red.release.gpu.global.add.u32 [%0], %1;"
                     :: "l"(ack), "r"(1u) : "memory");
        if ((c % NCTA_DIR) == 0) {
            unsigned v;
            do {
                asm volatile("ld.acquire.gpu.global.u32 %0, [%1];"
                             : "=r"(v) : "l"(ack) : "memory");
            } while (v < NCTA_DIR);
            *cnt = 0;
            *ack = 0;
            __threadfence();
        }
    }
}

// =============================================================================
// Fused head (k-chunk 160): linear -> softmax over BATCH dim -> angles.
// =============================================================================
#define HCHUNK 160
__global__ __launch_bounds__(640)
void head_kernel(const float* __restrict__ wlin, const float* __restrict__ blin,
                 const float* __restrict__ alphabet)
{
    int l = blockIdx.x;
    int tid = threadIdx.x;
    int j = tid >> 5, b = tid & 31;

    __shared__ float hs[HCHUNK * 32];
    __shared__ float ps[20][32];
    __shared__ float sa[60], ca[60];

    if (tid < 60) { float v = alphabet[tid]; sa[tid] = sinf(v); ca[tid] = cosf(v); }

    float acc = blin[j];
    const float* hb = g_h1 + (long)l * (H2 * BATCH);
    const float* w = wlin + j * H2;
    for (int k0 = 0; k0 < H2; k0 += HCHUNK) {
        __syncthreads();
#pragma unroll
        for (int i = 0; i < (HCHUNK * 32) / 640; i++)
            hs[tid + 640 * i] = hb[k0 * 32 + tid + 640 * i];
        __syncthreads();
#pragma unroll 8
        for (int k = 0; k < HCHUNK; k += 4) {
            float4 w4 = *(const float4*)(w + k0 + k);
            acc += w4.x * hs[(k + 0) * 32 + b];
            acc += w4.y * hs[(k + 1) * 32 + b];
            acc += w4.z * hs[(k + 2) * 32 + b];
            acc += w4.w * hs[(k + 3) * 32 + b];
        }
    }
    float m = acc;
#pragma unroll
    for (int o = 16; o; o >>= 1) m = fmaxf(m, __shfl_xor_sync(0xffffffffu, m, o));
    float e = expf(acc - m);
    float ssum = e;
#pragma unroll
    for (int o = 16; o; o >>= 1) ssum += __shfl_xor_sync(0xffffffffu, ssum, o);
    ps[j][b] = e / ssum;
    __syncthreads();

    if (tid < 96) {
        int b2 = tid / 3, i = tid - b2 * 3;
        float ssin = 0.f, scos = 0.f;
#pragma unroll
        for (int jj = 0; jj < 20; jj++) {
            float p = ps[jj][b2];
            ssin += p * sa[jj * 3 + i];
            scos += p * ca[jj * 3 + i];
        }
        g_ang[l * 96 + b2 * 3 + i] = atan2f(ssin, scos);
    }
}

// =============================================================================
// NeRF backbone extension (unchanged).
// =============================================================================
__global__ void nerf_kernel(float* __restrict__ out)
{
    int b = threadIdx.x;
    float ax = 0.f,   ay = 0.f,   az = 0.f;
    float bx = 100.f, by = 0.f,   bz = 0.f;
    float cx = 200.f, cy = 100.f, cz = 0.f;

    const float BL0 = 145.801f, BL1 = 152.326f, BL2 = 132.868f;
    const float TH0 = 2.124f,   TH1 = 1.941f,   TH2 = 2.028f;
    float d0a = -BL0 * cosf(TH0), d1a = BL0 * sinf(TH0);
    float d0b = -BL1 * cosf(TH1), d1b = BL1 * sinf(TH1);
    float d0c = -BL2 * cosf(TH2), d1c = BL2 * sinf(TH2);

    for (int s = 0; s < NCOORD; s++) {
        float phi = g_ang[s * 32 + b];
        int m = s - (s / 3) * 3;
        float d0 = (m == 0) ? d0a : (m == 1) ? d0b : d0c;
        float rs = (m == 0) ? d1a : (m == 1) ? d1b : d1c;

        float vx = cx - bx, vy = cy - by, vz = cz - bz;
        float inv = 1.f / (sqrtf(vx * vx + vy * vy + vz * vz) + 1e-12f);
        float bcx = vx * inv, bcy = vy * inv, bcz = vz * inv;

        float ux = bx - ax, uy = by - ay, uz = bz - az;
        float nx = uy * bcz - uz * bcy;
        float ny = uz * bcx - ux * bcz;
        float nz = ux * bcy - uy * bcx;
        float invn = 1.f / (sqrtf(nx * nx + ny * ny + nz * nz) + 1e-12f);
        nx *= invn; ny *= invn; nz *= invn;

        float mx = ny * bcz - nz * bcy;
        float my = nz * bcx - nx * bcz;
        float mz = nx * bcy - ny * bcx;

        float sp, cp;
        sincosf(phi, &sp, &cp);
        float d1 = rs * cp, d2 = rs * sp;

        float dx = cx + d0 * bcx + d1 * mx + d2 * nx;
        float dy = cy + d0 * bcy + d1 * my + d2 * ny;
        float dz = cz + d0 * bcz + d1 * mz + d2 * nz;

        out[s * 96 + b * 3 + 0] = dx;
        out[s * 96 + b * 3 + 1] = dy;
        out[s * 96 + b * 3 + 2] = dz;

        ax = bx; ay = by; az = bz;
        bx = cx; by = cy; bz = cz;
        cx = dx; cy = dy; cz = dz;
    }
}

// =============================================================================
extern "C" void kernel_launch(void* const* d_in, const int* in_sizes, int n_in,
                              void* d_out, int out_size)
{
    const float* x     = (const float*)d_in[0];
    const float* wih0  = (const float*)d_in[1];
    const float* whh0  = (const float*)d_in[2];
    const float* bih0  = (const float*)d_in[3];
    const float* bhh0  = (const float*)d_in[4];
    const float* wih1  = (const float*)d_in[5];
    const float* whh1  = (const float*)d_in[6];
    const float* bih1  = (const float*)d_in[7];
    const float* bhh1  = (const float*)d_in[8];
    const float* wlin  = (const float*)d_in[9];
    const float* blin  = (const float*)d_in[10];
    const float* alpha = (const float*)d_in[11];
    float* out = (float*)d_out;

    static int attr_done = 0;
    if (!attr_done) {
        cudaFuncSetAttribute(lstm_persist,
                             cudaFuncAttributeMaxDynamicSharedMemorySize, SMEM_LSTM);
        cudaFuncSetAttribute(gemm1_mma,
                             cudaFuncAttributeMaxDynamicSharedMemorySize, MM_SMEM);
        attr_done = 1;
    }

    float* G0p; cudaGetSymbolAddress((void**)&G0p, g_G0);
    float* G1p; cudaGetSymbolAddress((void**)&G1p, g_G1);

    // Layer 0 input-side pre-activations: G0 = x @ Wih0^T + biases (fp32, K=41)
    gemm_gates<<<dim3(50, 175), 256>>>(x, wih0, bih0, bhh0, G0p, DIN, DIN, 0);

    // Weight conversion for layer-1 GEMM (independent of lstm0)
    conv_w<<<20000, 256>>>(wih1);

    // Layer 0 recurrence (fp16 MMA inner matvec, 2 passes)
    lstm_persist<<<100, 256, SMEM_LSTM>>>(whh0, 0);

    // h0 -> single fp16 row-major
    conv_h<<<LSEQ, 256>>>();

    // Layer 1 input-side pre-activations via fp16 warp MMA (2 passes)
    gemm1_mma<<<dim3(50, 175), 256, MM_SMEM>>>(bih1, bhh1, G1p);

    // Layer 1 recurrence
    lstm_persist<<<100, 256, SMEM_LSTM>>>(whh1, 1);

    // Head: linear -> softmax(batch dim) -> angles
    head_kernel<<<LSEQ, 640>>>(wlin, blin, alpha);

    // NeRF extension -> output coords [2100][32][3]
    nerf_kernel<<<1, 32>>>(out);
}

// round 13
// speedup vs baseline: 8.1560x; 1.2501x over previous
#include <cuda_runtime.h>
#include <cuda_bf16.h>
#include <cuda_fp16.h>
#include <math.h>
#include <stdint.h>

// Problem constants
#define LSEQ 700
#define BATCH 32
#define DIN 41
#define HID 800
#define GATES 3200          // 4*HID
#define H2 1600             // 2*HID
#define NCOORD 2100         // 3*LSEQ

// ---------------- device scratch (allocation-free rule: __device__ globals) ---
__device__ float g_G0[2L * LSEQ * GATES * BATCH];   // [2][700][3200][32]
__device__ float g_G1[2L * LSEQ * GATES * BATCH];
__device__ float g_h1[LSEQ * H2 * BATCH];           // layer-1 h (fp32, for head)
__device__ float g_ang[LSEQ * BATCH * 3];
__device__ unsigned g_cnt[4];
__device__ unsigned g_ack[4];
// fp16 operands for layer-1 input GEMM
__device__ unsigned short g_Ahi16[22400L * 1600];   // h0 fp16 [row=t*32+b][k]
__device__ unsigned g_Bhi[6400 * 800];              // Wih1 hi [col][k/2]
__device__ unsigned g_Blo[6400 * 800];              // Wih1 lo (residual)
// fp16 h state for recurrence MMA: [dir][batch][k]
__device__ unsigned short g_hbf16[2 * 32 * 800];

// ---------------- fp16 pack/split helpers -------------------------------------
__device__ __forceinline__ unsigned packh2(float a, float b)
{
    __half2 h = __floats2half2_rn(a, b);
    return *(unsigned*)&h;
}
__device__ __forceinline__ void splith2(float a, float b,
                                        unsigned& hi, unsigned& lo)
{
    __half ha = __float2half_rn(a), hb2 = __float2half_rn(b);
    __half la = __float2half_rn(a - __half2float(ha));
    __half lb = __float2half_rn(b - __half2float(hb2));
    hi = ((unsigned)__half_as_ushort(hb2) << 16) | __half_as_ushort(ha);
    lo = ((unsigned)__half_as_ushort(lb) << 16) | __half_as_ushort(la);
}
__device__ __forceinline__ void st_u16_cg(unsigned short* p, unsigned short v)
{
    asm volatile("st.global.cg.u16 [%0], %1;" :: "l"(p), "h"(v) : "memory");
}

// ---------------- packed fp32x2 helpers --------------------------------------
__device__ __forceinline__ void ffma2(unsigned long long& d,
                                      unsigned long long a,
                                      unsigned long long b)
{
    asm("fma.rn.f32x2 %0, %1, %2, %3;" : "=l"(d) : "l"(a), "l"(b), "l"(d));
}
__device__ __forceinline__ unsigned long long dupf(float x)
{
    unsigned long long r;
    asm("mov.b64 %0, {%1, %1};" : "=l"(r) : "f"(x));
    return r;
}
__device__ __forceinline__ float2 unpackf(unsigned long long u)
{
    float2 f;
    asm("mov.b64 {%0, %1}, %2;" : "=f"(f.x), "=f"(f.y) : "l"(u));
    return f;
}
__device__ __forceinline__ float sigf(float x) { return 1.f / (1.f + expf(-x)); }

// ---------------- warp MMA fp16 ------------------------------------------------
__device__ __forceinline__ void mma16816h(float* d, const unsigned* a,
                                          const unsigned* b)
{
    asm volatile(
        "mma.sync.aligned.m16n8k16.row.col.f32.f16.f16.f32 "
        "{%0,%1,%2,%3}, {%4,%5,%6,%7}, {%8,%9}, {%0,%1,%2,%3};"
        : "+f"(d[0]), "+f"(d[1]), "+f"(d[2]), "+f"(d[3])
        : "r"(a[0]), "r"(a[1]), "r"(a[2]), "r"(a[3]), "r"(b[0]), "r"(b[1]));
}

// =============================================================================
// Tiled fp32 GEMM (f32x2) — used ONLY for layer 0 (K=41).
// =============================================================================
__global__ __launch_bounds__(256, 2)
void gemm_gates(const float* __restrict__ A, const float* __restrict__ B,
                const float* __restrict__ bias1, const float* __restrict__ bias2,
                float* __restrict__ Gout, int K, int ldb, int amode)
{
    __shared__ float As[16][128];
    __shared__ float Bs[16][128];
    int tid  = threadIdx.x;
    int row0 = blockIdx.y * 128;
    int col0 = blockIdx.x * 128;
    int tx = tid & 15, ty = tid >> 4;

    unsigned long long acc2[8][4];
#pragma unroll
    for (int m = 0; m < 8; m++)
#pragma unroll
        for (int n = 0; n < 4; n++) acc2[m][n] = 0ull;

    for (int kt = 0; kt < K; kt += 16) {
#pragma unroll
        for (int ii = 0; ii < 8; ii++) {
            int i = tid + 256 * ii;
            int kk = i >> 7, r = i & 127;
            int row = row0 + r;
            int k = kt + kk;
            float v = 0.f;
            if (k < K) {
                if (amode == 0) v = A[(row & 31) * (LSEQ * DIN) + (row >> 5) * DIN + k];
                else            v = 0.f;
            }
            As[kk][r] = v;
        }
#pragma unroll
        for (int ii = 0; ii < 8; ii++) {
            int i = tid + 256 * ii;
            int c = i >> 4, kk = i & 15;
            int k = kt + kk;
            Bs[kk][c] = (k < K) ? B[(col0 + c) * ldb + k] : 0.f;
        }
        __syncthreads();
#pragma unroll
        for (int kk = 0; kk < 16; kk++) {
            float a[8];
            *(float4*)&a[0] = *(const float4*)&As[kk][ty * 8];
            *(float4*)&a[4] = *(const float4*)&As[kk][ty * 8 + 4];
            ulonglong2 b01 = *(const ulonglong2*)&Bs[kk][tx * 8];
            ulonglong2 b23 = *(const ulonglong2*)&Bs[kk][tx * 8 + 4];
            unsigned long long bp[4] = { b01.x, b01.y, b23.x, b23.y };
#pragma unroll
            for (int m = 0; m < 8; m++) {
                unsigned long long am = dupf(a[m]);
#pragma unroll
                for (int n = 0; n < 4; n++) ffma2(acc2[m][n], am, bp[n]);
            }
        }
        __syncthreads();
    }

#pragma unroll
    for (int m = 0; m < 8; m++) {
        int row = row0 + ty * 8 + m;
        int t = row >> 5, b = row & 31;
#pragma unroll
        for (int n = 0; n < 4; n++) {
            float2 v = unpackf(acc2[m][n]);
            int c0 = col0 + tx * 8 + 2 * n;
#pragma unroll
            for (int q = 0; q < 2; q++) {
                int col = c0 + q;
                int dir = (col >= GATES) ? 1 : 0;
                int j = col - dir * GATES;
                float val = (q == 0 ? v.x : v.y) + bias1[col] + bias2[col];
                Gout[((dir * LSEQ + t) * GATES + j) * BATCH + b] = val;
            }
        }
    }
}

// =============================================================================
// conv_w: Wih1 [6400][1600] f32 -> fp16 hi/lo packed pairs [6400][800].
// =============================================================================
__global__ __launch_bounds__(256)
void conv_w(const float* __restrict__ W)
{
    long i = (long)blockIdx.x * 256 + threadIdx.x;
    if (i >= 6400L * 800) return;
    float2 v = *(const float2*)(W + 2 * i);
    unsigned hi, lo;
    splith2(v.x, v.y, hi, lo);
    g_Bhi[i] = hi;
    g_Blo[i] = lo;
}

// =============================================================================
// gemm1_mma: G1 = h0 @ Wih1^T + biases via fp16 warp MMA, 2 passes.
// A (h0 fp16) comes directly from lstm_persist layer-0 output (g_Ahi16).
// =============================================================================
#define MM_STRIDE 36
#define MM_ASZ (128 * MM_STRIDE)
#define MM_SMEM (3 * MM_ASZ * 4)                    // 55296 bytes

__global__ __launch_bounds__(256, 2)
void gemm1_mma(const float* __restrict__ bias1, const float* __restrict__ bias2,
               float* __restrict__ Gout)
{
    extern __shared__ unsigned sm[];
    unsigned* Ah = sm;
    unsigned* Bh = Ah + MM_ASZ;
    unsigned* Bl = Bh + MM_ASZ;

    const unsigned* Asrc = (const unsigned*)g_Ahi16;   // [row][k/2] packed pairs

    int tid = threadIdx.x;
    int wid = tid >> 5, lane = tid & 31;
    int g = lane >> 2, tig = lane & 3;
    int col0 = blockIdx.x * 128;
    int row0 = blockIdx.y * 128;
    int m0 = (wid & 3) * 32;
    int n0 = (wid >> 2) * 64;

    float acc[2][8][4];
#pragma unroll
    for (int mt = 0; mt < 2; mt++)
#pragma unroll
        for (int nt = 0; nt < 8; nt++)
#pragma unroll
            for (int q = 0; q < 4; q++) acc[mt][nt][q] = 0.f;

    int sr = tid >> 4, skq = tid & 15;

    for (int ch = 0; ch < 25; ch++) {
        __syncthreads();
#pragma unroll
        for (int it = 0; it < 8; it++) {
            int rr = sr + it * 16;
            long ao = (long)(row0 + rr) * 800 + ch * 32 + 2 * skq;
            long bo = (long)(col0 + rr) * 800 + ch * 32 + 2 * skq;
            *(uint2*)(Ah + rr * MM_STRIDE + 2 * skq) = *(const uint2*)(Asrc + ao);
            *(uint2*)(Bh + rr * MM_STRIDE + 2 * skq) = *(const uint2*)(g_Bhi + bo);
            *(uint2*)(Bl + rr * MM_STRIDE + 2 * skq) = *(const uint2*)(g_Blo + bo);
        }
        __syncthreads();

#pragma unroll
        for (int kk = 0; kk < 4; kk++) {
            int kpb = kk * 8;
            unsigned bh[8][2], bl[8][2];
#pragma unroll
            for (int nt = 0; nt < 8; nt++) {
                int br = (n0 + nt * 8 + g) * MM_STRIDE + kpb + tig;
                bh[nt][0] = Bh[br];     bh[nt][1] = Bh[br + 4];
                bl[nt][0] = Bl[br];     bl[nt][1] = Bl[br + 4];
            }
#pragma unroll
            for (int mt = 0; mt < 2; mt++) {
                int ar0 = (m0 + mt * 16 + g) * MM_STRIDE + kpb + tig;
                int ar1 = ar0 + 8 * MM_STRIDE;
                unsigned ah[4] = { Ah[ar0], Ah[ar1], Ah[ar0 + 4], Ah[ar1 + 4] };
#pragma unroll
                for (int nt = 0; nt < 8; nt++) {
                    mma16816h(acc[mt][nt], ah, bh[nt]);
                    mma16816h(acc[mt][nt], ah, bl[nt]);
                }
            }
        }
    }

#pragma unroll
    for (int mt = 0; mt < 2; mt++) {
        int r0 = row0 + m0 + mt * 16 + g;
        int r1 = r0 + 8;
        int t0 = r0 >> 5, b0 = r0 & 31;
        int t1 = r1 >> 5, b1 = r1 & 31;
#pragma unroll
        for (int nt = 0; nt < 8; nt++) {
            int c0 = col0 + n0 + nt * 8 + 2 * tig;
#pragma unroll
            for (int q = 0; q < 2; q++) {
                int col = c0 + q;
                int dir = (col >= GATES) ? 1 : 0;
                int j = col - dir * GATES;
                float bb = bias1[col] + bias2[col];
                Gout[((long)(dir * LSEQ + t0) * GATES + j) * BATCH + b0] =
                    acc[mt][nt][q] + bb;
                Gout[((long)(dir * LSEQ + t1) * GATES + j) * BATCH + b1] =
                    acc[mt][nt][2 + q] + bb;
            }
        }
    }
}

// =============================================================================
// Persistent bidirectional LSTM recurrence — fp16 MMA, 2 passes, 512 threads.
// 16 warps: gate = w&3, khalf = (w>>2)&1, nhalf = w>>3 (2 n8-tiles each).
// Cell mapping: unit = warp-id (1 unit/thread, 32 batch lanes).
// Layer 0 writes fp16 h directly into g_Ahi16 (feeds gemm1; conv_h removed)
// and skips the fp32 h write. Layer 1 writes fp32 h for the head.
// Both layers maintain g_hbf16 (fp16 h state) for their own next step.
// =============================================================================
#define NCTA_DIR 50
#define WSTR 404
#define BSTR 84
#define LS_WW (64 * WSTR)                     // words per weight buffer
#define LS_B_OFF (2 * LS_WW * 4)              // 206848 bytes
#define SMEM_LSTM (LS_B_OFF + 2 * 64 * 32 * 4)  // + pb 16384 = 223232 bytes

__global__ __launch_bounds__(512, 1)
void lstm_persist(const float* __restrict__ Whh, int layer)
{
    extern __shared__ char smemc[];
    unsigned* wsH = (unsigned*)smemc;                  // [64][WSTR] fp16 hi pairs
    unsigned* wsL = wsH + LS_WW;                       // fp16 lo pairs
    unsigned* bs  = (unsigned*)(smemc + LS_B_OFF);     // [32][BSTR] fp16 h pairs
    float* pb = (float*)(smemc + LS_B_OFF);            // [2][64][32] overlaps bs

    const float* G = layer ? g_G1 : g_G0;

    int c   = blockIdx.x;
    int dir = c / NCTA_DIR;
    int ubase = (c % NCTA_DIR) * 16;
    int tid = threadIdx.x;
    int wid = tid >> 5, lane = tid & 31;
    int gate  = wid & 3;
    int khalf = (wid >> 2) & 1;
    int nhalf = wid >> 3;
    int g = lane >> 2, tig = lane & 3;
    // cell mapping: unit = wid (0..15), batch = lane
    int cb = lane;
    int lu = wid;                 // local unit
    int u  = ubase + lu;

    unsigned short* hb16 = g_hbf16 + dir * 32 * 800;   // [32][800]
    const unsigned* hb = (const unsigned*)hb16;        // [32][400] pair view

    unsigned* cnt = &g_cnt[layer * 2 + dir];
    unsigned* ack = &g_ack[layer * 2 + dir];

    // ---- convert Whh slice -> smem fp16 hi/lo (once) ----
    const float* Wd = Whh + (long)dir * GATES * HID;
    for (int i = tid; i < 64 * 400; i += 512) {
        int r = i / 400, kp = i % 400;
        int grow = (r >> 4) * HID + ubase + (r & 15);
        float v0 = Wd[(long)grow * HID + 2 * kp];
        float v1 = Wd[(long)grow * HID + 2 * kp + 1];
        unsigned hi, lo;
        splith2(v0, v1, hi, lo);
        wsH[r * WSTR + kp] = hi;
        wsL[r * WSTR + kp] = lo;
    }
    __syncthreads();

    float creg = 0.f;

    for (int s = 0; s < LSEQ; s++) {
        int t = dir ? (LSEQ - 1 - s) : s;

        // gate pre-activations (cell mapping), issued early
        long gb = ((long)(dir * LSEQ + t)) * GATES * BATCH;
        float gp[4];
#pragma unroll
        for (int g4 = 0; g4 < 4; g4++)
            gp[g4] = G[gb + (long)(g4 * HID + u) * BATCH + cb];

        float ds[4] = {0.f, 0.f, 0.f, 0.f};

        if (s > 0) {
            float acc[2][4];
#pragma unroll
            for (int ntl = 0; ntl < 2; ntl++)
#pragma unroll
                for (int q = 0; q < 4; q++) acc[ntl][q] = 0.f;

            for (int ch = 0; ch < 5; ch++) {
                __syncthreads();                       // bs free
#pragma unroll
                for (int ii = 0; ii < 5; ii++) {
                    int i = tid + 512 * ii;
                    int b = i / 80, kp = i - b * 80;
                    bs[b * BSTR + kp] = __ldcg(hb + b * 400 + ch * 80 + kp);
                }
                __syncthreads();                       // bs ready
#pragma unroll
                for (int ki = 0; ki < 5; ki++) {
                    int kk = khalf * 5 + ki;
                    int akp = ch * 80 + kk * 8 + tig;
                    int ar0 = (gate * 16 + g) * WSTR + akp;
                    int ar1 = ar0 + 8 * WSTR;
                    unsigned ah[4] = { wsH[ar0], wsH[ar1], wsH[ar0+4], wsH[ar1+4] };
                    unsigned al[4] = { wsL[ar0], wsL[ar1], wsL[ar0+4], wsL[ar1+4] };
                    int bkp = kk * 8 + tig;
#pragma unroll
                    for (int ntl = 0; ntl < 2; ntl++) {
                        int nt = nhalf * 2 + ntl;
                        int br = (nt * 8 + g) * BSTR + bkp;
                        unsigned bfr[2] = { bs[br], bs[br + 4] };
                        mma16816h(acc[ntl], ah, bfr);
                        mma16816h(acc[ntl], al, bfr);
                    }
                }
            }
            __syncthreads();                           // bs done -> pb reuse
            {
                float* pbW = pb + khalf * (64 * 32);
#pragma unroll
                for (int ntl = 0; ntl < 2; ntl++) {
                    int colb = (nhalf * 2 + ntl) * 8 + 2 * tig;
                    pbW[(gate * 16 + g) * 32 + colb]         = acc[ntl][0];
                    pbW[(gate * 16 + g) * 32 + colb + 1]     = acc[ntl][1];
                    pbW[(gate * 16 + g + 8) * 32 + colb]     = acc[ntl][2];
                    pbW[(gate * 16 + g + 8) * 32 + colb + 1] = acc[ntl][3];
                }
            }
            __syncthreads();
#pragma unroll
            for (int g4 = 0; g4 < 4; g4++) {
                int r = (g4 * 16 + lu) * 32 + cb;
                ds[g4] = pb[r] + pb[64 * 32 + r];
            }
            __syncthreads();                           // pb read before overwrite
        }

        // ---- LSTM cell (one unit) ----
        float ai = gp[0] + ds[0];
        float af = gp[1] + ds[1];
        float ag = gp[2] + ds[2];
        float ao = gp[3] + ds[3];

        creg = sigf(af) * creg + sigf(ai) * tanhf(ag);
        float hv = sigf(ao) * tanhf(creg);

        if (layer) {
            __stcg(g_h1 + ((long)t * H2 + dir * HID + u) * BATCH + cb, hv);
        } else {
            // direct fp16 into gemm1's A operand: row = t*32+b, k = dir*800+u
            st_u16_cg(g_Ahi16 + ((long)(t * 32 + cb) * 1600 + dir * 800 + u),
                      __half_as_ushort(__float2half_rn(hv)));
        }
        // fp16 h state for next step's MMA
        st_u16_cg(hb16 + cb * 800 + u, __half_as_ushort(__float2half_rn(hv)));

        // ---- grid barrier over this direction's 50 CTAs ----
        __syncthreads();
        if (tid == 0) {
            asm volatile("red.release.gpu.global.add.u32 [%0], %1;"
                         :: "l"(cnt), "r"(1u) : "memory");
            unsigned target = (unsigned)(s + 1) * NCTA_DIR;
            unsigned v;
            do {
                asm volatile("ld.acquire.gpu.global.u32 %0, [%1];"
                             : "=r"(v) : "l"(cnt) : "memory");
            } while (v < target);
        }
        __syncthreads();
    }

    // ---- replay-safe counter reset via ack ----
    if (tid == 0) {
        asm volatile("red.release.gpu.global.add.u32 [%0], %1;"
                     :: "l"(ack), "r"(1u) : "memory");
        if ((c % NCTA_DIR) == 0) {
            unsigned v;
            do {
                asm volatile("ld.acquire.gpu.global.u32 %0, [%1];"
                             : "=r"(v) : "l"(ack) : "memory");
            } while (v < NCTA_DIR);
            *cnt = 0;
            *ack = 0;
            __threadfence();
        }
    }
}

// =============================================================================
// Fused head (k-chunk 160): linear -> softmax over BATCH dim -> angles.
// =============================================================================
#define HCHUNK 160
__global__ __launch_bounds__(640)
void head_kernel(const float* __restrict__ wlin, const float* __restrict__ blin,
                 const float* __restrict__ alphabet)
{
    int l = blockIdx.x;
    int tid = threadIdx.x;
    int j = tid >> 5, b = tid & 31;

    __shared__ float hs[HCHUNK * 32];
    __shared__ float ps[20][32];
    __shared__ float sa[60], ca[60];

    if (tid < 60) { float v = alphabet[tid]; sa[tid] = sinf(v); ca[tid] = cosf(v); }

    float acc = blin[j];
    const float* hb = g_h1 + (long)l * (H2 * BATCH);
    const float* w = wlin + j * H2;
    for (int k0 = 0; k0 < H2; k0 += HCHUNK) {
        __syncthreads();
#pragma unroll
        for (int i = 0; i < (HCHUNK * 32) / 640; i++)
            hs[tid + 640 * i] = hb[k0 * 32 + tid + 640 * i];
        __syncthreads();
#pragma unroll 8
        for (int k = 0; k < HCHUNK; k += 4) {
            float4 w4 = *(const float4*)(w + k0 + k);
            acc += w4.x * hs[(k + 0) * 32 + b];
            acc += w4.y * hs[(k + 1) * 32 + b];
            acc += w4.z * hs[(k + 2) * 32 + b];
            acc += w4.w * hs[(k + 3) * 32 + b];
        }
    }
    float m = acc;
#pragma unroll
    for (int o = 16; o; o >>= 1) m = fmaxf(m, __shfl_xor_sync(0xffffffffu, m, o));
    float e = expf(acc - m);
    float ssum = e;
#pragma unroll
    for (int o = 16; o; o >>= 1) ssum += __shfl_xor_sync(0xffffffffu, ssum, o);
    ps[j][b] = e / ssum;
    __syncthreads();

    if (tid < 96) {
        int b2 = tid / 3, i = tid - b2 * 3;
        float ssin = 0.f, scos = 0.f;
#pragma unroll
        for (int jj = 0; jj < 20; jj++) {
            float p = ps[jj][b2];
            ssin += p * sa[jj * 3 + i];
            scos += p * ca[jj * 3 + i];
        }
        g_ang[l * 96 + b2 * 3 + i] = atan2f(ssin, scos);
    }
}

// =============================================================================
// NeRF backbone extension (unchanged).
// =============================================================================
__global__ void nerf_kernel(float* __restrict__ out)
{
    int b = threadIdx.x;
    float ax = 0.f,   ay = 0.f,   az = 0.f;
    float bx = 100.f, by = 0.f,   bz = 0.f;
    float cx = 200.f, cy = 100.f, cz = 0.f;

    const float BL0 = 145.801f, BL1 = 152.326f, BL2 = 132.868f;
    const float TH0 = 2.124f,   TH1 = 1.941f,   TH2 = 2.028f;
    float d0a = -BL0 * cosf(TH0), d1a = BL0 * sinf(TH0);
    float d0b = -BL1 * cosf(TH1), d1b = BL1 * sinf(TH1);
    float d0c = -BL2 * cosf(TH2), d1c = BL2 * sinf(TH2);

    for (int s = 0; s < NCOORD; s++) {
        float phi = g_ang[s * 32 + b];
        int m = s - (s / 3) * 3;
        float d0 = (m == 0) ? d0a : (m == 1) ? d0b : d0c;
        float rs = (m == 0) ? d1a : (m == 1) ? d1b : d1c;

        float vx = cx - bx, vy = cy - by, vz = cz - bz;
        float inv = 1.f / (sqrtf(vx * vx + vy * vy + vz * vz) + 1e-12f);
        float bcx = vx * inv, bcy = vy * inv, bcz = vz * inv;

        float ux = bx - ax, uy = by - ay, uz = bz - az;
        float nx = uy * bcz - uz * bcy;
        float ny = uz * bcx - ux * bcz;
        float nz = ux * bcy - uy * bcx;
        float invn = 1.f / (sqrtf(nx * nx + ny * ny + nz * nz) + 1e-12f);
        nx *= invn; ny *= invn; nz *= invn;

        float mx = ny * bcz - nz * bcy;
        float my = nz * bcx - nx * bcz;
        float mz = nx * bcy - ny * bcx;

        float sp, cp;
        sincosf(phi, &sp, &cp);
        float d1 = rs * cp, d2 = rs * sp;

        float dx = cx + d0 * bcx + d1 * mx + d2 * nx;
        float dy = cy + d0 * bcy + d1 * my + d2 * ny;
        float dz = cz + d0 * bcz + d1 * mz + d2 * nz;

        out[s * 96 + b * 3 + 0] = dx;
        out[s * 96 + b * 3 + 1] = dy;
        out[s * 96 + b * 3 + 2] = dz;

        ax = bx; ay = by; az = bz;
        bx = cx; by = cy; bz = cz;
        cx = dx; cy = dy; cz = dz;
    }
}

// =============================================================================
extern "C" void kernel_launch(void* const* d_in, const int* in_sizes, int n_in,
                              void* d_out, int out_size)
{
    const float* x     = (const float*)d_in[0];
    const float* wih0  = (const float*)d_in[1];
    const float* whh0  = (const float*)d_in[2];
    const float* bih0  = (const float*)d_in[3];
    const float* bhh0  = (const float*)d_in[4];
    const float* wih1  = (const float*)d_in[5];
    const float* whh1  = (const float*)d_in[6];
    const float* bih1  = (const float*)d_in[7];
    const float* bhh1  = (const float*)d_in[8];
    const float* wlin  = (const float*)d_in[9];
    const float* blin  = (const float*)d_in[10];
    const float* alpha = (const float*)d_in[11];
    float* out = (float*)d_out;

    static int attr_done = 0;
    if (!attr_done) {
        cudaFuncSetAttribute(lstm_persist,
                             cudaFuncAttributeMaxDynamicSharedMemorySize, SMEM_LSTM);
        cudaFuncSetAttribute(gemm1_mma,
                             cudaFuncAttributeMaxDynamicSharedMemorySize, MM_SMEM);
        attr_done = 1;
    }

    float* G0p; cudaGetSymbolAddress((void**)&G0p, g_G0);
    float* G1p; cudaGetSymbolAddress((void**)&G1p, g_G1);

    // Layer 0 input-side pre-activations: G0 = x @ Wih0^T + biases (fp32, K=41)
    gemm_gates<<<dim3(50, 175), 256>>>(x, wih0, bih0, bhh0, G0p, DIN, DIN, 0);

    // Weight conversion for layer-1 GEMM (independent of lstm0)
    conv_w<<<20000, 256>>>(wih1);

    // Layer 0 recurrence (writes fp16 h directly into gemm1's A operand)
    lstm_persist<<<100, 512, SMEM_LSTM>>>(whh0, 0);

    // Layer 1 input-side pre-activations via fp16 warp MMA (2 passes)
    gemm1_mma<<<dim3(50, 175), 256, MM_SMEM>>>(bih1, bhh1, G1p);

    // Layer 1 recurrence
    lstm_persist<<<100, 512, SMEM_LSTM>>>(whh1, 1);

    // Head: linear -> softmax(batch dim) -> angles
    head_kernel<<<LSEQ, 640>>>(wlin, blin, alpha);

    // NeRF extension -> output coords [2100][32][3]
    nerf_kernel<<<1, 32>>>(out);
}

// round 14
// speedup vs baseline: 11.5085x; 1.4110x over previous
#include <cuda_runtime.h>
#include <cuda_bf16.h>
#include <cuda_fp16.h>
#include <math.h>
#include <stdint.h>

// Problem constants
#define LSEQ 700
#define BATCH 32
#define DIN 41
#define HID 800
#define GATES 3200          // 4*HID
#define H2 1600             // 2*HID
#define NCOORD 2100         // 3*LSEQ

// ---------------- device scratch (allocation-free rule: __device__ globals) ---
__device__ float g_G0[2L * LSEQ * GATES * BATCH];   // [2][700][3200][32]
__device__ float g_G1[2L * LSEQ * GATES * BATCH];
__device__ float g_h1[LSEQ * H2 * BATCH];           // layer-1 h (fp32, for head)
__device__ float g_ang[LSEQ * BATCH * 3];
__device__ unsigned g_cnt[4];
__device__ unsigned g_ack[4];
// fp16 operands for layer-1 input GEMM
__device__ unsigned short g_Ahi16[22400L * 1600];   // h0 fp16 [row=t*32+b][k]
__device__ unsigned g_Bhi[6400 * 800];              // Wih1 fp16 [col][k/2]
// fp16 h state for recurrence MMA: [dir][batch][k]
__device__ unsigned short g_hbf16[2 * 32 * 800];

// ---------------- fp16 helpers -------------------------------------------------
__device__ __forceinline__ unsigned packh2(float a, float b)
{
    __half2 h = __floats2half2_rn(a, b);
    return *(unsigned*)&h;
}
__device__ __forceinline__ void st_u16_cg(unsigned short* p, unsigned short v)
{
    asm volatile("st.global.cg.u16 [%0], %1;" :: "l"(p), "h"(v) : "memory");
}

// ---------------- packed fp32x2 helpers --------------------------------------
__device__ __forceinline__ void ffma2(unsigned long long& d,
                                      unsigned long long a,
                                      unsigned long long b)
{
    asm("fma.rn.f32x2 %0, %1, %2, %3;" : "=l"(d) : "l"(a), "l"(b), "l"(d));
}
__device__ __forceinline__ unsigned long long dupf(float x)
{
    unsigned long long r;
    asm("mov.b64 %0, {%1, %1};" : "=l"(r) : "f"(x));
    return r;
}
__device__ __forceinline__ float2 unpackf(unsigned long long u)
{
    float2 f;
    asm("mov.b64 {%0, %1}, %2;" : "=f"(f.x), "=f"(f.y) : "l"(u));
    return f;
}
__device__ __forceinline__ float sigf(float x) { return 1.f / (1.f + expf(-x)); }

// ---------------- warp MMA fp16 ------------------------------------------------
__device__ __forceinline__ void mma16816h(float* d, const unsigned* a,
                                          const unsigned* b)
{
    asm volatile(
        "mma.sync.aligned.m16n8k16.row.col.f32.f16.f16.f32 "
        "{%0,%1,%2,%3}, {%4,%5,%6,%7}, {%8,%9}, {%0,%1,%2,%3};"
        : "+f"(d[0]), "+f"(d[1]), "+f"(d[2]), "+f"(d[3])
        : "r"(a[0]), "r"(a[1]), "r"(a[2]), "r"(a[3]), "r"(b[0]), "r"(b[1]));
}

// =============================================================================
// Tiled fp32 GEMM (f32x2) — used ONLY for layer 0 (K=41).
// =============================================================================
__global__ __launch_bounds__(256, 2)
void gemm_gates(const float* __restrict__ A, const float* __restrict__ B,
                const float* __restrict__ bias1, const float* __restrict__ bias2,
                float* __restrict__ Gout, int K, int ldb, int amode)
{
    __shared__ float As[16][128];
    __shared__ float Bs[16][128];
    int tid  = threadIdx.x;
    int row0 = blockIdx.y * 128;
    int col0 = blockIdx.x * 128;
    int tx = tid & 15, ty = tid >> 4;

    unsigned long long acc2[8][4];
#pragma unroll
    for (int m = 0; m < 8; m++)
#pragma unroll
        for (int n = 0; n < 4; n++) acc2[m][n] = 0ull;

    for (int kt = 0; kt < K; kt += 16) {
#pragma unroll
        for (int ii = 0; ii < 8; ii++) {
            int i = tid + 256 * ii;
            int kk = i >> 7, r = i & 127;
            int row = row0 + r;
            int k = kt + kk;
            float v = 0.f;
            if (k < K && amode == 0)
                v = A[(row & 31) * (LSEQ * DIN) + (row >> 5) * DIN + k];
            As[kk][r] = v;
        }
#pragma unroll
        for (int ii = 0; ii < 8; ii++) {
            int i = tid + 256 * ii;
            int c = i >> 4, kk = i & 15;
            int k = kt + kk;
            Bs[kk][c] = (k < K) ? B[(col0 + c) * ldb + k] : 0.f;
        }
        __syncthreads();
#pragma unroll
        for (int kk = 0; kk < 16; kk++) {
            float a[8];
            *(float4*)&a[0] = *(const float4*)&As[kk][ty * 8];
            *(float4*)&a[4] = *(const float4*)&As[kk][ty * 8 + 4];
            ulonglong2 b01 = *(const ulonglong2*)&Bs[kk][tx * 8];
            ulonglong2 b23 = *(const ulonglong2*)&Bs[kk][tx * 8 + 4];
            unsigned long long bp[4] = { b01.x, b01.y, b23.x, b23.y };
#pragma unroll
            for (int m = 0; m < 8; m++) {
                unsigned long long am = dupf(a[m]);
#pragma unroll
                for (int n = 0; n < 4; n++) ffma2(acc2[m][n], am, bp[n]);
            }
        }
        __syncthreads();
    }

#pragma unroll
    for (int m = 0; m < 8; m++) {
        int row = row0 + ty * 8 + m;
        int t = row >> 5, b = row & 31;
#pragma unroll
        for (int n = 0; n < 4; n++) {
            float2 v = unpackf(acc2[m][n]);
            int c0 = col0 + tx * 8 + 2 * n;
#pragma unroll
            for (int q = 0; q < 2; q++) {
                int col = c0 + q;
                int dir = (col >= GATES) ? 1 : 0;
                int j = col - dir * GATES;
                float val = (q == 0 ? v.x : v.y) + bias1[col] + bias2[col];
                Gout[((dir * LSEQ + t) * GATES + j) * BATCH + b] = val;
            }
        }
    }
}

// =============================================================================
// conv_w: Wih1 [6400][1600] f32 -> fp16 packed pairs [6400][800].
// =============================================================================
__global__ __launch_bounds__(256)
void conv_w(const float* __restrict__ W)
{
    long i = (long)blockIdx.x * 256 + threadIdx.x;
    if (i >= 6400L * 800) return;
    float2 v = *(const float2*)(W + 2 * i);
    g_Bhi[i] = packh2(v.x, v.y);
}

// =============================================================================
// gemm1_mma: G1 = h0 @ Wih1^T + biases via pure fp16 warp MMA (1 pass).
// =============================================================================
#define MM_STRIDE 36
#define MM_ASZ (128 * MM_STRIDE)
#define MM_SMEM (2 * MM_ASZ * 4)                    // 36864 bytes

__global__ __launch_bounds__(256, 2)
void gemm1_mma(const float* __restrict__ bias1, const float* __restrict__ bias2,
               float* __restrict__ Gout)
{
    extern __shared__ unsigned sm[];
    unsigned* Ah = sm;
    unsigned* Bh = Ah + MM_ASZ;

    const unsigned* Asrc = (const unsigned*)g_Ahi16;   // [row][k/2] packed pairs

    int tid = threadIdx.x;
    int wid = tid >> 5, lane = tid & 31;
    int g = lane >> 2, tig = lane & 3;
    int col0 = blockIdx.x * 128;
    int row0 = blockIdx.y * 128;
    int m0 = (wid & 3) * 32;
    int n0 = (wid >> 2) * 64;

    float acc[2][8][4];
#pragma unroll
    for (int mt = 0; mt < 2; mt++)
#pragma unroll
        for (int nt = 0; nt < 8; nt++)
#pragma unroll
            for (int q = 0; q < 4; q++) acc[mt][nt][q] = 0.f;

    int sr = tid >> 4, skq = tid & 15;

    for (int ch = 0; ch < 25; ch++) {
        __syncthreads();
#pragma unroll
        for (int it = 0; it < 8; it++) {
            int rr = sr + it * 16;
            long ao = (long)(row0 + rr) * 800 + ch * 32 + 2 * skq;
            long bo = (long)(col0 + rr) * 800 + ch * 32 + 2 * skq;
            *(uint2*)(Ah + rr * MM_STRIDE + 2 * skq) = *(const uint2*)(Asrc + ao);
            *(uint2*)(Bh + rr * MM_STRIDE + 2 * skq) = *(const uint2*)(g_Bhi + bo);
        }
        __syncthreads();

#pragma unroll
        for (int kk = 0; kk < 4; kk++) {
            int kpb = kk * 8;
            unsigned bh[8][2];
#pragma unroll
            for (int nt = 0; nt < 8; nt++) {
                int br = (n0 + nt * 8 + g) * MM_STRIDE + kpb + tig;
                bh[nt][0] = Bh[br];     bh[nt][1] = Bh[br + 4];
            }
#pragma unroll
            for (int mt = 0; mt < 2; mt++) {
                int ar0 = (m0 + mt * 16 + g) * MM_STRIDE + kpb + tig;
                int ar1 = ar0 + 8 * MM_STRIDE;
                unsigned ah[4] = { Ah[ar0], Ah[ar1], Ah[ar0 + 4], Ah[ar1 + 4] };
#pragma unroll
                for (int nt = 0; nt < 8; nt++)
                    mma16816h(acc[mt][nt], ah, bh[nt]);
            }
        }
    }

#pragma unroll
    for (int mt = 0; mt < 2; mt++) {
        int r0 = row0 + m0 + mt * 16 + g;
        int r1 = r0 + 8;
        int t0 = r0 >> 5, b0 = r0 & 31;
        int t1 = r1 >> 5, b1 = r1 & 31;
#pragma unroll
        for (int nt = 0; nt < 8; nt++) {
            int c0 = col0 + n0 + nt * 8 + 2 * tig;
#pragma unroll
            for (int q = 0; q < 2; q++) {
                int col = c0 + q;
                int dir = (col >= GATES) ? 1 : 0;
                int j = col - dir * GATES;
                float bb = bias1[col] + bias2[col];
                Gout[((long)(dir * LSEQ + t0) * GATES + j) * BATCH + b0] =
                    acc[mt][nt][q] + bb;
                Gout[((long)(dir * LSEQ + t1) * GATES + j) * BATCH + b1] =
                    acc[mt][nt][2 + q] + bb;
            }
        }
    }
}

// =============================================================================
// Persistent bidirectional LSTM recurrence — pure fp16 MMA (1 pass),
// 512 threads / 16 warps: gate = w&3, khalf = (w>>2)&1, nhalf = w>>3.
// FULL h staged in ONE chunk per step (51.7KB, stride 404 conflict-free);
// separate pb buffer (no aliasing). 5 syncthreads/step total.
// Layer 0 writes fp16 h directly into g_Ahi16; layer 1 writes fp32 for head.
// =============================================================================
#define NCTA_DIR 50
#define WSTR 404
#define LS_WW (64 * WSTR)                       // weight words (fp16 pairs)
#define LS_BS_OFF (LS_WW * 4)                   // 103424
#define LS_BW (32 * WSTR)                       // h words
#define LS_PB_OFF (LS_BS_OFF + LS_BW * 4)       // 103424+51712 = 155136
#define SMEM_LSTM (LS_PB_OFF + 2 * 64 * 32 * 4) // +16384 = 171520 bytes

__global__ __launch_bounds__(512, 1)
void lstm_persist(const float* __restrict__ Whh, int layer)
{
    extern __shared__ char smemc[];
    unsigned* wsH = (unsigned*)smemc;                  // [64][WSTR] fp16 pairs
    unsigned* bs  = (unsigned*)(smemc + LS_BS_OFF);    // [32][WSTR] fp16 h pairs
    float* pb = (float*)(smemc + LS_PB_OFF);           // [2][64][32]

    const float* G = layer ? g_G1 : g_G0;

    int c   = blockIdx.x;
    int dir = c / NCTA_DIR;
    int ubase = (c % NCTA_DIR) * 16;
    int tid = threadIdx.x;
    int wid = tid >> 5, lane = tid & 31;
    int gate  = wid & 3;
    int khalf = (wid >> 2) & 1;
    int nhalf = wid >> 3;
    int g = lane >> 2, tig = lane & 3;
    // cell mapping: unit = warp-id (0..15), batch = lane
    int cb = lane;
    int lu = wid;
    int u  = ubase + lu;

    unsigned short* hb16 = g_hbf16 + dir * 32 * 800;   // [32][800]
    const unsigned* hb = (const unsigned*)hb16;        // [32][400] pair view

    unsigned* cnt = &g_cnt[layer * 2 + dir];
    unsigned* ack = &g_ack[layer * 2 + dir];

    // ---- convert Whh slice -> smem fp16 (once) ----
    const float* Wd = Whh + (long)dir * GATES * HID;
    for (int i = tid; i < 64 * 400; i += 512) {
        int r = i / 400, kp = i % 400;
        int grow = (r >> 4) * HID + ubase + (r & 15);
        float v0 = Wd[(long)grow * HID + 2 * kp];
        float v1 = Wd[(long)grow * HID + 2 * kp + 1];
        wsH[r * WSTR + kp] = packh2(v0, v1);
    }
    __syncthreads();

    float creg = 0.f;

    for (int s = 0; s < LSEQ; s++) {
        int t = dir ? (LSEQ - 1 - s) : s;

        // gate pre-activations (cell mapping), issued early
        long gb = ((long)(dir * LSEQ + t)) * GATES * BATCH;
        float gp[4];
#pragma unroll
        for (int g4 = 0; g4 < 4; g4++)
            gp[g4] = G[gb + (long)(g4 * HID + u) * BATCH + cb];

        float ds[4] = {0.f, 0.f, 0.f, 0.f};

        if (s > 0) {
            // ---- stage FULL h (32 x 400 pair-words) in one shot ----
            __syncthreads();                           // bs free (prev MMA done)
#pragma unroll
            for (int ii = 0; ii < 25; ii++) {
                int i = tid + 512 * ii;
                int b = i / 400, kp = i - b * 400;
                bs[b * WSTR + kp] = __ldcg(hb + i);
            }
            __syncthreads();                           // bs ready

            float acc[2][4];
#pragma unroll
            for (int ntl = 0; ntl < 2; ntl++)
#pragma unroll
                for (int q = 0; q < 4; q++) acc[ntl][q] = 0.f;

#pragma unroll
            for (int ki = 0; ki < 25; ki++) {
                int kk = khalf * 25 + ki;
                int akp = kk * 8 + tig;
                int ar0 = (gate * 16 + g) * WSTR + akp;
                int ar1 = ar0 + 8 * WSTR;
                unsigned ah[4] = { wsH[ar0], wsH[ar1], wsH[ar0+4], wsH[ar1+4] };
#pragma unroll
                for (int ntl = 0; ntl < 2; ntl++) {
                    int nt = nhalf * 2 + ntl;
                    int br = (nt * 8 + g) * WSTR + akp;
                    unsigned bfr[2] = { bs[br], bs[br + 4] };
                    mma16816h(acc[ntl], ah, bfr);
                }
            }

            // publish partials (pb separate buffer; no sync needed before)
            {
                float* pbW = pb + khalf * (64 * 32);
#pragma unroll
                for (int ntl = 0; ntl < 2; ntl++) {
                    int colb = (nhalf * 2 + ntl) * 8 + 2 * tig;
                    pbW[(gate * 16 + g) * 32 + colb]         = acc[ntl][0];
                    pbW[(gate * 16 + g) * 32 + colb + 1]     = acc[ntl][1];
                    pbW[(gate * 16 + g + 8) * 32 + colb]     = acc[ntl][2];
                    pbW[(gate * 16 + g + 8) * 32 + colb + 1] = acc[ntl][3];
                }
            }
            __syncthreads();                           // pb ready
#pragma unroll
            for (int g4 = 0; g4 < 4; g4++) {
                int r = (g4 * 16 + lu) * 32 + cb;
                ds[g4] = pb[r] + pb[64 * 32 + r];
            }
        }

        // ---- LSTM cell (one unit) ----
        float ai = gp[0] + ds[0];
        float af = gp[1] + ds[1];
        float ag = gp[2] + ds[2];
        float ao = gp[3] + ds[3];

        creg = sigf(af) * creg + sigf(ai) * tanhf(ag);
        float hv = sigf(ao) * tanhf(creg);

        if (layer) {
            __stcg(g_h1 + ((long)t * H2 + dir * HID + u) * BATCH + cb, hv);
        } else {
            st_u16_cg(g_Ahi16 + ((long)(t * 32 + cb) * 1600 + dir * 800 + u),
                      __half_as_ushort(__float2half_rn(hv)));
        }
        st_u16_cg(hb16 + cb * 800 + u, __half_as_ushort(__float2half_rn(hv)));

        // ---- grid barrier over this direction's 50 CTAs ----
        __syncthreads();
        if (tid == 0) {
            asm volatile("red.release.gpu.global.add.u32 [%0], %1;"
                         :: "l"(cnt), "r"(1u) : "memory");
            unsigned target = (unsigned)(s + 1) * NCTA_DIR;
            unsigned v;
            do {
                asm volatile("ld.acquire.gpu.global.u32 %0, [%1];"
                             : "=r"(v) : "l"(cnt) : "memory");
            } while (v < target);
        }
        __syncthreads();
    }

    // ---- replay-safe counter reset via ack ----
    if (tid == 0) {
        asm volatile("red.release.gpu.global.add.u32 [%0], %1;"
                     :: "l"(ack), "r"(1u) : "memory");
        if ((c % NCTA_DIR) == 0) {
            unsigned v;
            do {
                asm volatile("ld.acquire.gpu.global.u32 %0, [%1];"
                             : "=r"(v) : "l"(ack) : "memory");
            } while (v < NCTA_DIR);
            *cnt = 0;
            *ack = 0;
            __threadfence();
        }
    }
}

// =============================================================================
// Fused head (k-chunk 160): linear -> softmax over BATCH dim -> angles.
// =============================================================================
#define HCHUNK 160
__global__ __launch_bounds__(640)
void head_kernel(const float* __restrict__ wlin, const float* __restrict__ blin,
                 const float* __restrict__ alphabet)
{
    int l = blockIdx.x;
    int tid = threadIdx.x;
    int j = tid >> 5, b = tid & 31;

    __shared__ float hs[HCHUNK * 32];
    __shared__ float ps[20][32];
    __shared__ float sa[60], ca[60];

    if (tid < 60) { float v = alphabet[tid]; sa[tid] = sinf(v); ca[tid] = cosf(v); }

    float acc = blin[j];
    const float* hb = g_h1 + (long)l * (H2 * BATCH);
    const float* w = wlin + j * H2;
    for (int k0 = 0; k0 < H2; k0 += HCHUNK) {
        __syncthreads();
#pragma unroll
        for (int i = 0; i < (HCHUNK * 32) / 640; i++)
            hs[tid + 640 * i] = hb[k0 * 32 + tid + 640 * i];
        __syncthreads();
#pragma unroll 8
        for (int k = 0; k < HCHUNK; k += 4) {
            float4 w4 = *(const float4*)(w + k0 + k);
            acc += w4.x * hs[(k + 0) * 32 + b];
            acc += w4.y * hs[(k + 1) * 32 + b];
            acc += w4.z * hs[(k + 2) * 32 + b];
            acc += w4.w * hs[(k + 3) * 32 + b];
        }
    }
    float m = acc;
#pragma unroll
    for (int o = 16; o; o >>= 1) m = fmaxf(m, __shfl_xor_sync(0xffffffffu, m, o));
    float e = expf(acc - m);
    float ssum = e;
#pragma unroll
    for (int o = 16; o; o >>= 1) ssum += __shfl_xor_sync(0xffffffffu, ssum, o);
    ps[j][b] = e / ssum;
    __syncthreads();

    if (tid < 96) {
        int b2 = tid / 3, i = tid - b2 * 3;
        float ssin = 0.f, scos = 0.f;
#pragma unroll
        for (int jj = 0; jj < 20; jj++) {
            float p = ps[jj][b2];
            ssin += p * sa[jj * 3 + i];
            scos += p * ca[jj * 3 + i];
        }
        g_ang[l * 96 + b2 * 3 + i] = atan2f(ssin, scos);
    }
}

// =============================================================================
// NeRF backbone extension (unchanged).
// =============================================================================
__global__ void nerf_kernel(float* __restrict__ out)
{
    int b = threadIdx.x;
    float ax = 0.f,   ay = 0.f,   az = 0.f;
    float bx = 100.f, by = 0.f,   bz = 0.f;
    float cx = 200.f, cy = 100.f, cz = 0.f;

    const float BL0 = 145.801f, BL1 = 152.326f, BL2 = 132.868f;
    const float TH0 = 2.124f,   TH1 = 1.941f,   TH2 = 2.028f;
    float d0a = -BL0 * cosf(TH0), d1a = BL0 * sinf(TH0);
    float d0b = -BL1 * cosf(TH1), d1b = BL1 * sinf(TH1);
    float d0c = -BL2 * cosf(TH2), d1c = BL2 * sinf(TH2);

    for (int s = 0; s < NCOORD; s++) {
        float phi = g_ang[s * 32 + b];
        int m = s - (s / 3) * 3;
        float d0 = (m == 0) ? d0a : (m == 1) ? d0b : d0c;
        float rs = (m == 0) ? d1a : (m == 1) ? d1b : d1c;

        float vx = cx - bx, vy = cy - by, vz = cz - bz;
        float inv = 1.f / (sqrtf(vx * vx + vy * vy + vz * vz) + 1e-12f);
        float bcx = vx * inv, bcy = vy * inv, bcz = vz * inv;

        float ux = bx - ax, uy = by - ay, uz = bz - az;
        float nx = uy * bcz - uz * bcy;
        float ny = uz * bcx - ux * bcz;
        float nz = ux * bcy - uy * bcx;
        float invn = 1.f / (sqrtf(nx * nx + ny * ny + nz * nz) + 1e-12f);
        nx *= invn; ny *= invn; nz *= invn;

        float mx = ny * bcz - nz * bcy;
        float my = nz * bcx - nx * bcz;
        float mz = nx * bcy - ny * bcx;

        float sp, cp;
        sincosf(phi, &sp, &cp);
        float d1 = rs * cp, d2 = rs * sp;

        float dx = cx + d0 * bcx + d1 * mx + d2 * nx;
        float dy = cy + d0 * bcy + d1 * my + d2 * ny;
        float dz = cz + d0 * bcz + d1 * mz + d2 * nz;

        out[s * 96 + b * 3 + 0] = dx;
        out[s * 96 + b * 3 + 1] = dy;
        out[s * 96 + b * 3 + 2] = dz;

        ax = bx; ay = by; az = bz;
        bx = cx; by = cy; bz = cz;
        cx = dx; cy = dy; cz = dz;
    }
}

// =============================================================================
extern "C" void kernel_launch(void* const* d_in, const int* in_sizes, int n_in,
                              void* d_out, int out_size)
{
    const float* x     = (const float*)d_in[0];
    const float* wih0  = (const float*)d_in[1];
    const float* whh0  = (const float*)d_in[2];
    const float* bih0  = (const float*)d_in[3];
    const float* bhh0  = (const float*)d_in[4];
    const float* wih1  = (const float*)d_in[5];
    const float* whh1  = (const float*)d_in[6];
    const float* bih1  = (const float*)d_in[7];
    const float* bhh1  = (const float*)d_in[8];
    const float* wlin  = (const float*)d_in[9];
    const float* blin  = (const float*)d_in[10];
    const float* alpha = (const float*)d_in[11];
    float* out = (float*)d_out;

    static int attr_done = 0;
    if (!attr_done) {
        cudaFuncSetAttribute(lstm_persist,
                             cudaFuncAttributeMaxDynamicSharedMemorySize, SMEM_LSTM);
        cudaFuncSetAttribute(gemm1_mma,
                             cudaFuncAttributeMaxDynamicSharedMemorySize, MM_SMEM);
        attr_done = 1;
    }

    float* G0p; cudaGetSymbolAddress((void**)&G0p, g_G0);
    float* G1p; cudaGetSymbolAddress((void**)&G1p, g_G1);

    // Layer 0 input-side pre-activations: G0 = x @ Wih0^T + biases (fp32, K=41)
    gemm_gates<<<dim3(50, 175), 256>>>(x, wih0, bih0, bhh0, G0p, DIN, DIN, 0);

    // Weight conversion for layer-1 GEMM (independent of lstm0)
    conv_w<<<20000, 256>>>(wih1);

    // Layer 0 recurrence (writes fp16 h directly into gemm1's A operand)
    lstm_persist<<<100, 512, SMEM_LSTM>>>(whh0, 0);

    // Layer 1 input-side pre-activations via pure fp16 warp MMA (1 pass)
    gemm1_mma<<<dim3(50, 175), 256, MM_SMEM>>>(bih1, bhh1, G1p);

    // Layer 1 recurrence
    lstm_persist<<<100, 512, SMEM_LSTM>>>(whh1, 1);

    // Head: linear -> softmax(batch dim) -> angles
    head_kernel<<<LSEQ, 640>>>(wlin, blin, alpha);

    // NeRF extension -> output coords [2100][32][3]
    nerf_kernel<<<1, 32>>>(out);
}